// round 9
// baseline (speedup 1.0000x reference)
#include <cuda_runtime.h>
#include <math.h>

#define NROWS 32768          // B*S = 128*256
#define INV_SQRT_HD 0.17677669529663687f   // 1/sqrt(32)

typedef unsigned long long u64;

// Scratch (allocation-free rule: __device__ globals)
__device__ float g_weff[128 * 512];   // fused weights [k][col]; col: 0-127 q, 128-255 k, 256-383 v, 384-511 wo
__device__ float g_q[NROWS * 128];    // [b][h][s][d]
__device__ float g_k[NROWS * 128];
__device__ float g_v[NROWS * 128];
__device__ float g_o[NROWS * 128];    // [b][s][h*32+d]
__device__ float2 g_rope[256 * 16];   // {cos, sin} per (s, pair)

// ---------------------------------------------------------------------------
// f32x2 packed helpers (Blackwell FFMA2 — PTX-only path, full fp32 precision)
// ---------------------------------------------------------------------------
__device__ __forceinline__ void ffma2(u64& d, u64 a, u64 b) {
    asm("fma.rn.f32x2 %0, %1, %2, %0;" : "+l"(d) : "l"(a), "l"(b));
}
__device__ __forceinline__ u64 add2(u64 a, u64 b) {
    u64 d; asm("add.rn.f32x2 %0, %1, %2;" : "=l"(d) : "l"(a), "l"(b)); return d;
}
__device__ __forceinline__ u64 mul2(u64 a, u64 b) {
    u64 d; asm("mul.rn.f32x2 %0, %1, %2;" : "=l"(d) : "l"(a), "l"(b)); return d;
}
__device__ __forceinline__ u64 pack2(float lo, float hi) {
    u64 d;
    asm("mov.b64 %0, {%1, %2};" : "=l"(d) : "r"(__float_as_uint(lo)), "r"(__float_as_uint(hi)));
    return d;
}
__device__ __forceinline__ void unpack2(u64 v, float& lo, float& hi) {
    unsigned a, b;
    asm("mov.b64 {%0, %1}, %2;" : "=r"(a), "=r"(b) : "l"(v));
    lo = __uint_as_float(a); hi = __uint_as_float(b);
}

// ---------------------------------------------------------------------------
// Kernel 0a: fold LoRA into effective weights, store transposed for GEMM.
// ---------------------------------------------------------------------------
__global__ void fuse_weights(const float* __restrict__ wq, const float* __restrict__ wk,
                             const float* __restrict__ wv, const float* __restrict__ wo,
                             const float* __restrict__ Aq, const float* __restrict__ Bq,
                             const float* __restrict__ Ak, const float* __restrict__ Bk,
                             const float* __restrict__ Av, const float* __restrict__ Bv) {
    int col = blockIdx.x;           // 0..511
    int j = threadIdx.x;            // 0..127
    int g = col >> 7;
    int i = col & 127;
    const float* w = (g == 0) ? wq : (g == 1) ? wk : (g == 2) ? wv : wo;
    float acc = w[i * 128 + j];
    if (g < 3) {
        const float* A  = (g == 0) ? Aq : (g == 1) ? Ak : Av;
        const float* Bm = (g == 0) ? Bq : (g == 1) ? Bk : Bv;
        float s = 0.f;
#pragma unroll
        for (int r = 0; r < 8; r++) s += Bm[i * 8 + r] * A[r * 128 + j];
        acc += 2.0f * s;            // SCALING = 16/8
    }
    g_weff[j * 512 + col] = acc;
}

// ---------------------------------------------------------------------------
// Kernel 0b: RoPE cos/sin table
// ---------------------------------------------------------------------------
__global__ void rope_table() {
    int s = threadIdx.x;            // 0..255
#pragma unroll
    for (int p = 0; p < 16; p++) {
        float invf = powf(10000.0f, -(float)p / 16.0f);
        float ang = (float)s * invf;
        float sn, cs;
        sincosf(ang, &sn, &cs);
        g_rope[s * 16 + p] = make_float2(cs, sn);
    }
}

// ---------------------------------------------------------------------------
// FFMA2 GEMM mainloop: 128x128 CTA tile, 8 rows x 4 column-pairs per thread.
// A in smem pre-duplicated (a,a) as u64; B rows read as ulonglong2.
// ---------------------------------------------------------------------------
__device__ __forceinline__ void gemm128_body2(const float* __restrict__ Asrc, int m0,
                                              const float* __restrict__ Bsrc,
                                              u64 acc2[8][4],
                                              u64 (*As2)[32], float (*Bs)[128]) {
    int tx = threadIdx.x, ty = threadIdx.y;
    int tid = ty * 16 + tx;

    for (int kt = 0; kt < 4; kt++) {
        // A tile: 128 rows x 32 k, each float stored duplicated as u64
#pragma unroll
        for (int i = 0; i < 4; i++) {
            int idx = tid + i * 256;
            int r = idx >> 3, c4 = idx & 7;
            float4 v = *(const float4*)&Asrc[(m0 + r) * 128 + kt * 32 + c4 * 4];
            As2[r][c4 * 4]     = pack2(v.x, v.x);
            As2[r][c4 * 4 + 1] = pack2(v.y, v.y);
            As2[r][c4 * 4 + 2] = pack2(v.z, v.z);
            As2[r][c4 * 4 + 3] = pack2(v.w, v.w);
        }
        // B tile: 32 k x 128 n
#pragma unroll
        for (int i = 0; i < 4; i++) {
            int idx = tid + i * 256;
            int kr = idx >> 5, c4 = idx & 31;
            float4 v = *(const float4*)&Bsrc[(kt * 32 + kr) * 512 + c4 * 4];
            *(float4*)&Bs[kr][c4 * 4] = v;
        }
        __syncthreads();

#pragma unroll 8
        for (int kk = 0; kk < 32; kk++) {
            u64 a2[8];
#pragma unroll
            for (int i = 0; i < 8; i++) a2[i] = As2[ty * 8 + i][kk];   // broadcast LDS.64
            ulonglong2 b01 = *(const ulonglong2*)&Bs[kk][tx * 8];
            ulonglong2 b23 = *(const ulonglong2*)&Bs[kk][tx * 8 + 4];
#pragma unroll
            for (int i = 0; i < 8; i++) {
                ffma2(acc2[i][0], a2[i], b01.x);
                ffma2(acc2[i][1], a2[i], b01.y);
                ffma2(acc2[i][2], a2[i], b23.x);
                ffma2(acc2[i][3], a2[i], b23.y);
            }
        }
        __syncthreads();
    }
}

// ---------------------------------------------------------------------------
// Kernel 2: QKV projection (FFMA2) + RoPE epilogue + scatter
// ---------------------------------------------------------------------------
__global__ __launch_bounds__(256, 2) void qkv_gemm(const float* __restrict__ X) {
    __shared__ __align__(16) u64 As2[128][32];      // 32 KB
    __shared__ __align__(16) float Bs[32][128];     // 16 KB
    u64 acc2[8][4] = {};

    int m0 = blockIdx.x * 128;
    int g = blockIdx.y;                 // 0=q, 1=k, 2=v
    gemm128_body2(X, m0, g_weff + g * 128, acc2, As2, Bs);

    int tx = threadIdx.x, ty = threadIdx.y;
    float* dst = (g == 0) ? g_q : (g == 1) ? g_k : g_v;

#pragma unroll
    for (int i = 0; i < 8; i++) {
        int row = m0 + ty * 8 + i;
        int b = row >> 8, s = row & 255;
        if (g < 2) {
#pragma unroll
            for (int j = 0; j < 4; j++) {
                int col = tx * 8 + 2 * j;
                int h = col >> 5, d = col & 31;
                int p = d >> 1;
                float x1, x2;
                unpack2(acc2[i][j], x1, x2);
                float2 cs = g_rope[s * 16 + p];
                float2 o = make_float2(x1 * cs.x - x2 * cs.y,
                                       x1 * cs.y + x2 * cs.x);
                *(float2*)&dst[(((b << 2) + h) * 256 + s) * 32 + d] = o;
            }
        } else {
            float c[8];
            unpack2(acc2[i][0], c[0], c[1]);
            unpack2(acc2[i][1], c[2], c[3]);
            unpack2(acc2[i][2], c[4], c[5]);
            unpack2(acc2[i][3], c[6], c[7]);
            int col = tx * 8;
            int h = col >> 5, d = col & 31;
            float* dp = &dst[(((b << 2) + h) * 256 + s) * 32 + d];
            *(float4*)dp       = make_float4(c[0], c[1], c[2], c[3]);
            *(float4*)(dp + 4) = make_float4(c[4], c[5], c[6], c[7]);
        }
    }
}

// ---------------------------------------------------------------------------
// Kernel 4: output projection (FFMA2)
// ---------------------------------------------------------------------------
__global__ __launch_bounds__(256, 2) void out_gemm(float* __restrict__ out) {
    __shared__ __align__(16) u64 As2[128][32];
    __shared__ __align__(16) float Bs[32][128];
    u64 acc2[8][4] = {};

    int m0 = blockIdx.x * 128;
    gemm128_body2(g_o, m0, g_weff + 384, acc2, As2, Bs);

    int tx = threadIdx.x, ty = threadIdx.y;
#pragma unroll
    for (int i = 0; i < 8; i++) {
        int row = m0 + ty * 8 + i;
        float c[8];
        unpack2(acc2[i][0], c[0], c[1]);
        unpack2(acc2[i][1], c[2], c[3]);
        unpack2(acc2[i][2], c[4], c[5]);
        unpack2(acc2[i][3], c[6], c[7]);
        float* dp = &out[row * 128 + tx * 8];
        *(float4*)dp       = make_float4(c[0], c[1], c[2], c[3]);
        *(float4*)(dp + 4) = make_float4(c[4], c[5], c[6], c[7]);
    }
}

// ---------------------------------------------------------------------------
// Kernel 3: split-K causal attention, 2 rows per lane, FFMA2 mainloop.
// smem: Ksm (32KB) | Vsm (32KB) | s-partials (1KB). o-partials ALIAS Ksm
// after the mainloop (extra syncthreads) -> 65KB total -> 3 CTAs/SM.
// ---------------------------------------------------------------------------
__global__ __launch_bounds__(128, 3) void attn_split2() {
    extern __shared__ float sm[];
    float* Ksm = sm;                // 8192 floats (aliased by o-partials later)
    float* Vsm = sm + 8192;         // 8192 floats
    float* sArr = sm + 16384;       // 4 warps * 64 rows

    int t  = blockIdx.x;            // row block 0..3 (64 rows each)
    int bh = blockIdx.y;
    int kmax = 64 * (t + 1);
    const float* Qb = g_q + bh * 8192;
    const float4* Kb4 = (const float4*)(g_k + bh * 8192);
    const float4* Vb4 = (const float4*)(g_v + bh * 8192);
    int tid = threadIdx.x;

    int n4 = kmax * 8;
    for (int i = tid; i < n4; i += 128) {
        ((float4*)Ksm)[i] = Kb4[i];
        ((float4*)Vsm)[i] = Vb4[i];
    }
    __syncthreads();

    int w = tid >> 5, lane = tid & 31;
    int ra = 64 * t + lane;         // lower row
    int rb = ra + 32;               // upper row

    // Two Q rows, packed f32x2 and pre-scaled by 1/sqrt(hd)
    u64 q2a[16], q2b[16];
    {
        u64 inv2 = pack2(INV_SQRT_HD, INV_SQRT_HD);
        const ulonglong2* Qa = (const ulonglong2*)(Qb + ra * 32);
        const ulonglong2* Qc = (const ulonglong2*)(Qb + rb * 32);
#pragma unroll
        for (int i = 0; i < 8; i++) {
            ulonglong2 va = Qa[i], vb = Qc[i];
            q2a[2 * i]     = mul2(va.x, inv2);
            q2a[2 * i + 1] = mul2(va.y, inv2);
            q2b[2 * i]     = mul2(vb.x, inv2);
            q2b[2 * i + 1] = mul2(vb.y, inv2);
        }
    }

    u64 o2a[16] = {}, o2b[16] = {};
    float sa = 0.f, sb = 0.f;

    int C = 16 * (t + 1);           // keys per warp
    int k0 = w * C;
    int k1 = k0 + C;
    for (int k = k0; k < k1; k++) {
        const ulonglong2* Kr = (const ulonglong2*)(Ksm + k * 32);   // broadcast
        u64 da0 = 0, da1 = 0, db0 = 0, db1 = 0;
#pragma unroll
        for (int i = 0; i < 8; i++) {
            ulonglong2 kk2 = Kr[i];
            ffma2(da0, q2a[2 * i],     kk2.x);
            ffma2(da1, q2a[2 * i + 1], kk2.y);
            ffma2(db0, q2b[2 * i],     kk2.x);
            ffma2(db1, q2b[2 * i + 1], kk2.y);
        }
        float dal, dah, dbl, dbh;
        unpack2(add2(da0, da1), dal, dah);
        unpack2(add2(db0, db1), dbl, dbh);
        // Branchless causal mask: masked -> exp(-inf) = 0.
        float siga = (k <= ra) ? (dal + dah) : -INFINITY;
        float sigb = (k <= rb) ? (dbl + dbh) : -INFINITY;
        float ea = __expf(siga);
        float eb = __expf(sigb);
        sa += ea; sb += eb;
        u64 ea2 = pack2(ea, ea), eb2 = pack2(eb, eb);
        const ulonglong2* Vr = (const ulonglong2*)(Vsm + k * 32);   // broadcast
#pragma unroll
        for (int i = 0; i < 8; i++) {
            ulonglong2 vv = Vr[i];
            ffma2(o2a[2 * i],     ea2, vv.x);
            ffma2(o2a[2 * i + 1], ea2, vv.y);
            ffma2(o2b[2 * i],     eb2, vv.x);
            ffma2(o2b[2 * i + 1], eb2, vv.y);
        }
    }

    // All warps must finish reading K before o-partials overwrite it.
    __syncthreads();

    // o-partials alias Ksm: warp w, local row rl -> sm[w*2048 + rl*32 + d]
    {
        u64* Pa = (u64*)(sm + w * 2048 + lane * 32);
        u64* Pb = (u64*)(sm + w * 2048 + (lane + 32) * 32);
#pragma unroll
        for (int i = 0; i < 16; i++) { Pa[i] = o2a[i]; Pb[i] = o2b[i]; }
        sArr[w * 64 + lane]      = sa;
        sArr[w * 64 + lane + 32] = sb;
    }
    __syncthreads();

    // Reduce 4 warp partials: o (2048 floats) and s (64).
    for (int i = tid; i < 2048; i += 128) {
        sm[i] = sm[i] + sm[2048 + i] + sm[4096 + i] + sm[6144 + i];
    }
    if (tid < 64) {
        float ssum = sArr[tid] + sArr[64 + tid] + sArr[128 + tid] + sArr[192 + tid];
        sArr[tid] = 1.f / ssum;
    }
    __syncthreads();

    // Normalize + write: 64 rows x 8 float4 = 512 stores / 128 threads.
    int b = bh >> 2, h = bh & 3;
    for (int i = tid; i < 512; i += 128) {
        int rr = i >> 3;
        int d0 = (i & 7) * 4;
        float inv = sArr[rr];
        const float* R = sm + rr * 32 + d0;
        float4 ov = make_float4(R[0] * inv, R[1] * inv, R[2] * inv, R[3] * inv);
        *(float4*)&g_o[(((b << 8) + 64 * t + rr) * 128) + h * 32 + d0] = ov;
    }
}

// ---------------------------------------------------------------------------
extern "C" void kernel_launch(void* const* d_in, const int* in_sizes, int n_in,
                              void* d_out, int out_size) {
    const float* x  = (const float*)d_in[0];
    const float* wq = (const float*)d_in[1];
    const float* wk = (const float*)d_in[2];
    const float* wv = (const float*)d_in[3];
    const float* wo = (const float*)d_in[4];
    const float* Aq = (const float*)d_in[5];
    const float* Bq = (const float*)d_in[6];
    const float* Ak = (const float*)d_in[7];
    const float* Bk = (const float*)d_in[8];
    const float* Av = (const float*)d_in[9];
    const float* Bv = (const float*)d_in[10];
    float* out = (float*)d_out;

    fuse_weights<<<512, 128>>>(wq, wk, wv, wo, Aq, Bq, Ak, Bk, Av, Bv);
    rope_table<<<1, 256>>>();

    qkv_gemm<<<dim3(256, 3), dim3(16, 16)>>>(x);

    int smem_attn = (16384 + 256) * (int)sizeof(float);   // 66560
    cudaFuncSetAttribute(attn_split2, cudaFuncAttributeMaxDynamicSharedMemorySize, smem_attn);
    attn_split2<<<dim3(4, 512), 128, smem_attn>>>();

    out_gemm<<<256, dim3(16, 16)>>>(out);
}

// round 10
// speedup vs baseline: 1.0489x; 1.0489x over previous
#include <cuda_runtime.h>
#include <math.h>

#define NROWS 32768          // B*S = 128*256
#define INV_SQRT_HD 0.17677669529663687f   // 1/sqrt(32)

// Scratch (allocation-free rule: __device__ globals)
__device__ float g_weff[128 * 512];   // fused weights [k][col]; col: 0-127 q, 128-255 k, 256-383 v, 384-511 wo
__device__ float g_q[NROWS * 128];    // [b][h][s][d]
__device__ float g_k[NROWS * 128];
__device__ float g_v[NROWS * 128];
__device__ float g_o[NROWS * 128];    // [b][s][h*32+d]
__device__ float2 g_rope[256 * 16];   // {cos, sin} per (s, pair)

// ---------------------------------------------------------------------------
// Kernel 0a: fold LoRA into effective weights, store transposed for GEMM.
// ---------------------------------------------------------------------------
__global__ void fuse_weights(const float* __restrict__ wq, const float* __restrict__ wk,
                             const float* __restrict__ wv, const float* __restrict__ wo,
                             const float* __restrict__ Aq, const float* __restrict__ Bq,
                             const float* __restrict__ Ak, const float* __restrict__ Bk,
                             const float* __restrict__ Av, const float* __restrict__ Bv) {
    int col = blockIdx.x;           // 0..511
    int j = threadIdx.x;            // 0..127
    int g = col >> 7;
    int i = col & 127;
    const float* w = (g == 0) ? wq : (g == 1) ? wk : (g == 2) ? wv : wo;
    float acc = w[i * 128 + j];
    if (g < 3) {
        const float* A  = (g == 0) ? Aq : (g == 1) ? Ak : Av;
        const float* Bm = (g == 0) ? Bq : (g == 1) ? Bk : Bv;
        float s = 0.f;
#pragma unroll
        for (int r = 0; r < 8; r++) s += Bm[i * 8 + r] * A[r * 128 + j];
        acc += 2.0f * s;            // SCALING = 16/8
    }
    g_weff[j * 512 + col] = acc;
}

// ---------------------------------------------------------------------------
// Kernel 0b: RoPE cos/sin table
// ---------------------------------------------------------------------------
__global__ void rope_table() {
    int s = threadIdx.x;            // 0..255
#pragma unroll
    for (int p = 0; p < 16; p++) {
        float invf = powf(10000.0f, -(float)p / 16.0f);
        float ang = (float)s * invf;
        float sn, cs;
        sincosf(ang, &sn, &cs);
        g_rope[s * 16 + p] = make_float2(cs, sn);
    }
}

// ---------------------------------------------------------------------------
// Shared GEMM mainloop: 128x128 CTA tile, 8x8 per thread, BK=32. (round-5/8)
// ---------------------------------------------------------------------------
__device__ __forceinline__ void gemm128_body(const float* __restrict__ Asrc, int m0,
                                             const float* __restrict__ Bsrc,
                                             float acc[8][8],
                                             float (*As)[33], float (*Bs)[132]) {
    int tx = threadIdx.x, ty = threadIdx.y;
    int tid = ty * 16 + tx;

    for (int kt = 0; kt < 4; kt++) {
#pragma unroll
        for (int i = 0; i < 4; i++) {
            int idx = tid + i * 256;
            int r = idx >> 3, c4 = idx & 7;
            float4 v = *(const float4*)&Asrc[(m0 + r) * 128 + kt * 32 + c4 * 4];
            As[r][c4 * 4]     = v.x;
            As[r][c4 * 4 + 1] = v.y;
            As[r][c4 * 4 + 2] = v.z;
            As[r][c4 * 4 + 3] = v.w;
        }
#pragma unroll
        for (int i = 0; i < 4; i++) {
            int idx = tid + i * 256;
            int kr = idx >> 5, c4 = idx & 31;
            float4 v = *(const float4*)&Bsrc[(kt * 32 + kr) * 512 + c4 * 4];
            *(float4*)&Bs[kr][c4 * 4] = v;
        }
        __syncthreads();

#pragma unroll
        for (int kk = 0; kk < 32; kk++) {
            float a[8];
#pragma unroll
            for (int i = 0; i < 8; i++) a[i] = As[ty * 8 + i][kk];
            float4 b0 = *(const float4*)&Bs[kk][tx * 8];
            float4 b1 = *(const float4*)&Bs[kk][tx * 8 + 4];
            float bb[8] = {b0.x, b0.y, b0.z, b0.w, b1.x, b1.y, b1.z, b1.w};
#pragma unroll
            for (int i = 0; i < 8; i++)
#pragma unroll
                for (int j = 0; j < 8; j++) acc[i][j] += a[i] * bb[j];
        }
        __syncthreads();
    }
}

// ---------------------------------------------------------------------------
// Kernel 2: QKV projection + RoPE (round-8, unchanged)
// ---------------------------------------------------------------------------
__global__ __launch_bounds__(256, 2) void qkv_gemm(const float* __restrict__ X) {
    __shared__ float As[128][33];
    __shared__ float Bs[32][132];
    float acc[8][8] = {};

    int m0 = blockIdx.x * 128;
    int g = blockIdx.y;                 // 0=q, 1=k, 2=v
    gemm128_body(X, m0, g_weff + g * 128, acc, As, Bs);

    int tx = threadIdx.x, ty = threadIdx.y;
    float* dst = (g == 0) ? g_q : (g == 1) ? g_k : g_v;

#pragma unroll
    for (int i = 0; i < 8; i++) {
        int row = m0 + ty * 8 + i;
        int b = row >> 8, s = row & 255;
        if (g < 2) {
#pragma unroll
            for (int u = 0; u < 4; u++) {
                int col = tx * 8 + 2 * u;
                int h = col >> 5, d = col & 31;
                int p = d >> 1;
                float2 cs = g_rope[s * 16 + p];
                float x1 = acc[i][2 * u], x2 = acc[i][2 * u + 1];
                float2 o = make_float2(x1 * cs.x - x2 * cs.y,
                                       x1 * cs.y + x2 * cs.x);
                *(float2*)&dst[(((b << 2) + h) * 256 + s) * 32 + d] = o;
            }
        } else {
            int col = tx * 8;
            int h = col >> 5, d = col & 31;
            float* dp = &dst[(((b << 2) + h) * 256 + s) * 32 + d];
            *(float4*)dp       = make_float4(acc[i][0], acc[i][1], acc[i][2], acc[i][3]);
            *(float4*)(dp + 4) = make_float4(acc[i][4], acc[i][5], acc[i][6], acc[i][7]);
        }
    }
}

// ---------------------------------------------------------------------------
// Kernel 4: output projection (round-8, unchanged)
// ---------------------------------------------------------------------------
__global__ __launch_bounds__(256, 2) void out_gemm(float* __restrict__ out) {
    __shared__ float As[128][33];
    __shared__ float Bs[32][132];
    float acc[8][8] = {};

    int m0 = blockIdx.x * 128;
    gemm128_body(g_o, m0, g_weff + 384, acc, As, Bs);

    int tx = threadIdx.x, ty = threadIdx.y;
#pragma unroll
    for (int i = 0; i < 8; i++) {
        int row = m0 + ty * 8 + i;
        float* dp = &out[row * 128 + tx * 8];
        *(float4*)dp       = make_float4(acc[i][0], acc[i][1], acc[i][2], acc[i][3]);
        *(float4*)(dp + 4) = make_float4(acc[i][4], acc[i][5], acc[i][6], acc[i][7]);
    }
}

// ---------------------------------------------------------------------------
// Kernel 3: split-K causal attention, 2 rows per lane (round-8 scalar math)
// + round-9 smem aliasing: o-partials overwrite Ksm after the mainloop.
// smem = K 32KB | V 32KB | s-partials 1KB = 66.5KB -> 3 CTAs/SM.
// ---------------------------------------------------------------------------
__global__ __launch_bounds__(128, 3) void attn_split2() {
    extern __shared__ float sm[];
    float* Ksm = sm;                // 8192 floats (aliased by o-partials later)
    float* Vsm = sm + 8192;         // 8192 floats
    float* sArr = sm + 16384;       // 4 warps * 64 rows

    int t  = blockIdx.x;            // row block 0..3 (64 rows each)
    int bh = blockIdx.y;
    int kmax = 64 * (t + 1);
    const float* Qb = g_q + bh * 8192;
    const float4* Kb4 = (const float4*)(g_k + bh * 8192);
    const float4* Vb4 = (const float4*)(g_v + bh * 8192);
    int tid = threadIdx.x;

    int n4 = kmax * 8;
    for (int i = tid; i < n4; i += 128) {
        ((float4*)Ksm)[i] = Kb4[i];
        ((float4*)Vsm)[i] = Vb4[i];
    }
    __syncthreads();

    int w = tid >> 5, lane = tid & 31;
    int ra = 64 * t + lane;         // lower row
    int rb = ra + 32;               // upper row

    // Two Q rows in registers, pre-scaled by 1/sqrt(hd)
    float qa[32], qb[32];
    const float4* Qa4 = (const float4*)(Qb + ra * 32);
    const float4* Qb4r = (const float4*)(Qb + rb * 32);
#pragma unroll
    for (int i = 0; i < 8; i++) {
        float4 va = Qa4[i], vb = Qb4r[i];
        qa[i * 4]     = va.x * INV_SQRT_HD; qa[i * 4 + 1] = va.y * INV_SQRT_HD;
        qa[i * 4 + 2] = va.z * INV_SQRT_HD; qa[i * 4 + 3] = va.w * INV_SQRT_HD;
        qb[i * 4]     = vb.x * INV_SQRT_HD; qb[i * 4 + 1] = vb.y * INV_SQRT_HD;
        qb[i * 4 + 2] = vb.z * INV_SQRT_HD; qb[i * 4 + 3] = vb.w * INV_SQRT_HD;
    }

    float oa[32], ob[32];
#pragma unroll
    for (int d = 0; d < 32; d++) { oa[d] = 0.f; ob[d] = 0.f; }
    float sa = 0.f, sb = 0.f;

    int C = 16 * (t + 1);           // keys per warp
    int k0 = w * C;
    int k1 = k0 + C;
    for (int k = k0; k < k1; k++) {
        const float4* Kr = (const float4*)(Ksm + k * 32);   // broadcast
        float da0 = 0.f, da1 = 0.f, db0 = 0.f, db1 = 0.f;
#pragma unroll
        for (int i = 0; i < 8; i++) {
            float4 kv = Kr[i];
            da0 += qa[i * 4]     * kv.x;
            da1 += qa[i * 4 + 1] * kv.y;
            da0 += qa[i * 4 + 2] * kv.z;
            da1 += qa[i * 4 + 3] * kv.w;
            db0 += qb[i * 4]     * kv.x;
            db1 += qb[i * 4 + 1] * kv.y;
            db0 += qb[i * 4 + 2] * kv.z;
            db1 += qb[i * 4 + 3] * kv.w;
        }
        // Branchless causal mask: masked -> exp(-inf) = 0.
        float siga = (k <= ra) ? (da0 + da1) : -INFINITY;
        float sigb = (k <= rb) ? (db0 + db1) : -INFINITY;
        float ea = __expf(siga);
        float eb = __expf(sigb);
        sa += ea; sb += eb;
        const float4* Vr = (const float4*)(Vsm + k * 32);   // broadcast
#pragma unroll
        for (int i = 0; i < 8; i++) {
            float4 vv = Vr[i];
            oa[i * 4]     += ea * vv.x;
            oa[i * 4 + 1] += ea * vv.y;
            oa[i * 4 + 2] += ea * vv.z;
            oa[i * 4 + 3] += ea * vv.w;
            ob[i * 4]     += eb * vv.x;
            ob[i * 4 + 1] += eb * vv.y;
            ob[i * 4 + 2] += eb * vv.z;
            ob[i * 4 + 3] += eb * vv.w;
        }
    }

    // All warps must finish reading K before o-partials overwrite it.
    __syncthreads();

    // o-partials alias Ksm: warp w, local row rl -> sm[w*2048 + rl*32 + d]
    {
        float* Pa = sm + w * 2048 + lane * 32;
        float* Pb = sm + w * 2048 + (lane + 32) * 32;
#pragma unroll
        for (int i = 0; i < 8; i++) {
            ((float4*)Pa)[i] = make_float4(oa[4 * i], oa[4 * i + 1], oa[4 * i + 2], oa[4 * i + 3]);
            ((float4*)Pb)[i] = make_float4(ob[4 * i], ob[4 * i + 1], ob[4 * i + 2], ob[4 * i + 3]);
        }
        sArr[w * 64 + lane]      = sa;
        sArr[w * 64 + lane + 32] = sb;
    }
    __syncthreads();

    // Reduce 4 warp partials: o (2048 floats) and s (64).
    for (int i = tid; i < 2048; i += 128) {
        sm[i] = sm[i] + sm[2048 + i] + sm[4096 + i] + sm[6144 + i];
    }
    if (tid < 64) {
        float ssum = sArr[tid] + sArr[64 + tid] + sArr[128 + tid] + sArr[192 + tid];
        sArr[tid] = 1.f / ssum;
    }
    __syncthreads();

    // Normalize + write: 64 rows x 8 float4 = 512 stores / 128 threads.
    int b = bh >> 2, h = bh & 3;
    for (int i = tid; i < 512; i += 128) {
        int rr = i >> 3;
        int d0 = (i & 7) * 4;
        float inv = sArr[rr];
        const float* R = sm + rr * 32 + d0;
        float4 ov = make_float4(R[0] * inv, R[1] * inv, R[2] * inv, R[3] * inv);
        *(float4*)&g_o[(((b << 8) + 64 * t + rr) * 128) + h * 32 + d0] = ov;
    }
}

// ---------------------------------------------------------------------------
extern "C" void kernel_launch(void* const* d_in, const int* in_sizes, int n_in,
                              void* d_out, int out_size) {
    const float* x  = (const float*)d_in[0];
    const float* wq = (const float*)d_in[1];
    const float* wk = (const float*)d_in[2];
    const float* wv = (const float*)d_in[3];
    const float* wo = (const float*)d_in[4];
    const float* Aq = (const float*)d_in[5];
    const float* Bq = (const float*)d_in[6];
    const float* Ak = (const float*)d_in[7];
    const float* Bk = (const float*)d_in[8];
    const float* Av = (const float*)d_in[9];
    const float* Bv = (const float*)d_in[10];
    float* out = (float*)d_out;

    fuse_weights<<<512, 128>>>(wq, wk, wv, wo, Aq, Bq, Ak, Bk, Av, Bv);
    rope_table<<<1, 256>>>();

    qkv_gemm<<<dim3(256, 3), dim3(16, 16)>>>(x);

    int smem_attn = (16384 + 256) * (int)sizeof(float);   // 66560
    cudaFuncSetAttribute(attn_split2, cudaFuncAttributeMaxDynamicSharedMemorySize, smem_attn);
    attn_split2<<<dim3(4, 512), 128, smem_attn>>>();

    out_gemm<<<256, dim3(16, 16)>>>(out);
}

// round 11
// speedup vs baseline: 1.0545x; 1.0053x over previous
#include <cuda_runtime.h>
#include <math.h>

#define NROWS 32768          // B*S = 128*256
#define INV_SQRT_HD 0.17677669529663687f   // 1/sqrt(32)

// Scratch (allocation-free rule: __device__ globals)
__device__ float g_weff[128 * 512];   // fused weights [k][col]; col: 0-127 q, 128-255 k, 256-383 v, 384-511 wo
__device__ float g_q[NROWS * 128];    // [b][h][s][d]
__device__ float g_k[NROWS * 128];
__device__ float g_v[NROWS * 128];
__device__ float g_o[NROWS * 128];    // [b][s][h*32+d]
__device__ float2 g_rope[256 * 16];   // {cos, sin} per (s, pair)

// ---------------------------------------------------------------------------
// Kernel 0a: fold LoRA into effective weights, store transposed for GEMM.
// ---------------------------------------------------------------------------
__global__ void fuse_weights(const float* __restrict__ wq, const float* __restrict__ wk,
                             const float* __restrict__ wv, const float* __restrict__ wo,
                             const float* __restrict__ Aq, const float* __restrict__ Bq,
                             const float* __restrict__ Ak, const float* __restrict__ Bk,
                             const float* __restrict__ Av, const float* __restrict__ Bv) {
    int col = blockIdx.x;           // 0..511
    int j = threadIdx.x;            // 0..127
    int g = col >> 7;
    int i = col & 127;
    const float* w = (g == 0) ? wq : (g == 1) ? wk : (g == 2) ? wv : wo;
    float acc = w[i * 128 + j];
    if (g < 3) {
        const float* A  = (g == 0) ? Aq : (g == 1) ? Ak : Av;
        const float* Bm = (g == 0) ? Bq : (g == 1) ? Bk : Bv;
        float s = 0.f;
#pragma unroll
        for (int r = 0; r < 8; r++) s += Bm[i * 8 + r] * A[r * 128 + j];
        acc += 2.0f * s;            // SCALING = 16/8
    }
    g_weff[j * 512 + col] = acc;
}

// ---------------------------------------------------------------------------
// Kernel 0b: RoPE cos/sin table
// ---------------------------------------------------------------------------
__global__ void rope_table() {
    int s = threadIdx.x;            // 0..255
#pragma unroll
    for (int p = 0; p < 16; p++) {
        float invf = powf(10000.0f, -(float)p / 16.0f);
        float ang = (float)s * invf;
        float sn, cs;
        sincosf(ang, &sn, &cs);
        g_rope[s * 16 + p] = make_float2(cs, sn);
    }
}

// ---------------------------------------------------------------------------
// Shared GEMM mainloop: 128x128 CTA tile, 8x8 per thread, BK=32. (round-8)
// ---------------------------------------------------------------------------
__device__ __forceinline__ void gemm128_body(const float* __restrict__ Asrc, int m0,
                                             const float* __restrict__ Bsrc,
                                             float acc[8][8],
                                             float (*As)[33], float (*Bs)[132]) {
    int tx = threadIdx.x, ty = threadIdx.y;
    int tid = ty * 16 + tx;

    for (int kt = 0; kt < 4; kt++) {
#pragma unroll
        for (int i = 0; i < 4; i++) {
            int idx = tid + i * 256;
            int r = idx >> 3, c4 = idx & 7;
            float4 v = *(const float4*)&Asrc[(m0 + r) * 128 + kt * 32 + c4 * 4];
            As[r][c4 * 4]     = v.x;
            As[r][c4 * 4 + 1] = v.y;
            As[r][c4 * 4 + 2] = v.z;
            As[r][c4 * 4 + 3] = v.w;
        }
#pragma unroll
        for (int i = 0; i < 4; i++) {
            int idx = tid + i * 256;
            int kr = idx >> 5, c4 = idx & 31;
            float4 v = *(const float4*)&Bsrc[(kt * 32 + kr) * 512 + c4 * 4];
            *(float4*)&Bs[kr][c4 * 4] = v;
        }
        __syncthreads();

#pragma unroll
        for (int kk = 0; kk < 32; kk++) {
            float a[8];
#pragma unroll
            for (int i = 0; i < 8; i++) a[i] = As[ty * 8 + i][kk];
            float4 b0 = *(const float4*)&Bs[kk][tx * 8];
            float4 b1 = *(const float4*)&Bs[kk][tx * 8 + 4];
            float bb[8] = {b0.x, b0.y, b0.z, b0.w, b1.x, b1.y, b1.z, b1.w};
#pragma unroll
            for (int i = 0; i < 8; i++)
#pragma unroll
                for (int j = 0; j < 8; j++) acc[i][j] += a[i] * bb[j];
        }
        __syncthreads();
    }
}

// ---------------------------------------------------------------------------
// Kernel 2: QKV projection + RoPE (round-8, unchanged)
// ---------------------------------------------------------------------------
__global__ __launch_bounds__(256, 2) void qkv_gemm(const float* __restrict__ X) {
    __shared__ float As[128][33];
    __shared__ float Bs[32][132];
    float acc[8][8] = {};

    int m0 = blockIdx.x * 128;
    int g = blockIdx.y;                 // 0=q, 1=k, 2=v
    gemm128_body(X, m0, g_weff + g * 128, acc, As, Bs);

    int tx = threadIdx.x, ty = threadIdx.y;
    float* dst = (g == 0) ? g_q : (g == 1) ? g_k : g_v;

#pragma unroll
    for (int i = 0; i < 8; i++) {
        int row = m0 + ty * 8 + i;
        int b = row >> 8, s = row & 255;
        if (g < 2) {
#pragma unroll
            for (int u = 0; u < 4; u++) {
                int col = tx * 8 + 2 * u;
                int h = col >> 5, d = col & 31;
                int p = d >> 1;
                float2 cs = g_rope[s * 16 + p];
                float x1 = acc[i][2 * u], x2 = acc[i][2 * u + 1];
                float2 o = make_float2(x1 * cs.x - x2 * cs.y,
                                       x1 * cs.y + x2 * cs.x);
                *(float2*)&dst[(((b << 2) + h) * 256 + s) * 32 + d] = o;
            }
        } else {
            int col = tx * 8;
            int h = col >> 5, d = col & 31;
            float* dp = &dst[(((b << 2) + h) * 256 + s) * 32 + d];
            *(float4*)dp       = make_float4(acc[i][0], acc[i][1], acc[i][2], acc[i][3]);
            *(float4*)(dp + 4) = make_float4(acc[i][4], acc[i][5], acc[i][6], acc[i][7]);
        }
    }
}

// ---------------------------------------------------------------------------
// Kernel 4: output projection (round-8, unchanged)
// ---------------------------------------------------------------------------
__global__ __launch_bounds__(256, 2) void out_gemm(float* __restrict__ out) {
    __shared__ float As[128][33];
    __shared__ float Bs[32][132];
    float acc[8][8] = {};

    int m0 = blockIdx.x * 128;
    gemm128_body(g_o, m0, g_weff + 384, acc, As, Bs);

    int tx = threadIdx.x, ty = threadIdx.y;
#pragma unroll
    for (int i = 0; i < 8; i++) {
        int row = m0 + ty * 8 + i;
        float* dp = &out[row * 128 + tx * 8];
        *(float4*)dp       = make_float4(acc[i][0], acc[i][1], acc[i][2], acc[i][3]);
        *(float4*)(dp + 4) = make_float4(acc[i][4], acc[i][5], acc[i][6], acc[i][7]);
    }
}

// ---------------------------------------------------------------------------
// Kernel 3: split-K causal attention, 2 rows per lane, KEY LOOP UNROLLED x2.
// Two independent keys in flight per iteration -> doubled ILP to cover the
// dot-reduce + MUFU-exp dependency chain. 2 CTAs/SM (no reg cap).
// smem: K 32KB | V 32KB | s-partials 1KB; o-partials alias Ksm post-mainloop.
// ---------------------------------------------------------------------------
__global__ __launch_bounds__(128, 2) void attn_split2() {
    extern __shared__ float sm[];
    float* Ksm = sm;                // 8192 floats (aliased by o-partials later)
    float* Vsm = sm + 8192;         // 8192 floats
    float* sArr = sm + 16384;       // 4 warps * 64 rows

    int t  = blockIdx.x;            // row block 0..3 (64 rows each)
    int bh = blockIdx.y;
    int kmax = 64 * (t + 1);
    const float* Qb = g_q + bh * 8192;
    const float4* Kb4 = (const float4*)(g_k + bh * 8192);
    const float4* Vb4 = (const float4*)(g_v + bh * 8192);
    int tid = threadIdx.x;

    int n4 = kmax * 8;
    for (int i = tid; i < n4; i += 128) {
        ((float4*)Ksm)[i] = Kb4[i];
        ((float4*)Vsm)[i] = Vb4[i];
    }
    __syncthreads();

    int w = tid >> 5, lane = tid & 31;
    int ra = 64 * t + lane;         // lower row
    int rb = ra + 32;               // upper row

    // Two Q rows in registers, pre-scaled by 1/sqrt(hd)
    float qa[32], qb[32];
    const float4* Qa4 = (const float4*)(Qb + ra * 32);
    const float4* Qb4r = (const float4*)(Qb + rb * 32);
#pragma unroll
    for (int i = 0; i < 8; i++) {
        float4 va = Qa4[i], vb = Qb4r[i];
        qa[i * 4]     = va.x * INV_SQRT_HD; qa[i * 4 + 1] = va.y * INV_SQRT_HD;
        qa[i * 4 + 2] = va.z * INV_SQRT_HD; qa[i * 4 + 3] = va.w * INV_SQRT_HD;
        qb[i * 4]     = vb.x * INV_SQRT_HD; qb[i * 4 + 1] = vb.y * INV_SQRT_HD;
        qb[i * 4 + 2] = vb.z * INV_SQRT_HD; qb[i * 4 + 3] = vb.w * INV_SQRT_HD;
    }

    float oa[32], ob[32];
#pragma unroll
    for (int d = 0; d < 32; d++) { oa[d] = 0.f; ob[d] = 0.f; }
    float sa = 0.f, sb = 0.f;

    int C = 16 * (t + 1);           // keys per warp (even -> clean x2 unroll)
    int k0 = w * C;
    int k1 = k0 + C;
    for (int k = k0; k < k1; k += 2) {
        const float4* Kr0 = (const float4*)(Ksm + k * 32);         // broadcast
        const float4* Kr1 = (const float4*)(Ksm + (k + 1) * 32);   // broadcast
        float x0a = 0.f, y0a = 0.f, x0b = 0.f, y0b = 0.f;   // key k chains
        float x1a = 0.f, y1a = 0.f, x1b = 0.f, y1b = 0.f;   // key k+1 chains
#pragma unroll
        for (int i = 0; i < 8; i++) {
            float4 k0v = Kr0[i];
            float4 k1v = Kr1[i];
            x0a += qa[i * 4]     * k0v.x;
            y0a += qa[i * 4 + 1] * k0v.y;
            x0a += qa[i * 4 + 2] * k0v.z;
            y0a += qa[i * 4 + 3] * k0v.w;
            x0b += qb[i * 4]     * k0v.x;
            y0b += qb[i * 4 + 1] * k0v.y;
            x0b += qb[i * 4 + 2] * k0v.z;
            y0b += qb[i * 4 + 3] * k0v.w;
            x1a += qa[i * 4]     * k1v.x;
            y1a += qa[i * 4 + 1] * k1v.y;
            x1a += qa[i * 4 + 2] * k1v.z;
            y1a += qa[i * 4 + 3] * k1v.w;
            x1b += qb[i * 4]     * k1v.x;
            y1b += qb[i * 4 + 1] * k1v.y;
            x1b += qb[i * 4 + 2] * k1v.z;
            y1b += qb[i * 4 + 3] * k1v.w;
        }
        // Branchless causal mask: masked -> exp(-inf) = 0.
        float s0a = (k     <= ra) ? (x0a + y0a) : -INFINITY;
        float s0b = (k     <= rb) ? (x0b + y0b) : -INFINITY;
        float s1a = (k + 1 <= ra) ? (x1a + y1a) : -INFINITY;
        float s1b = (k + 1 <= rb) ? (x1b + y1b) : -INFINITY;
        float e0a = __expf(s0a);
        float e0b = __expf(s0b);
        float e1a = __expf(s1a);
        float e1b = __expf(s1b);
        sa += e0a + e1a;
        sb += e0b + e1b;
        const float4* Vr0 = (const float4*)(Vsm + k * 32);         // broadcast
        const float4* Vr1 = (const float4*)(Vsm + (k + 1) * 32);   // broadcast
#pragma unroll
        for (int i = 0; i < 8; i++) {
            float4 v0 = Vr0[i];
            float4 v1 = Vr1[i];
            oa[i * 4]     += e0a * v0.x;
            oa[i * 4 + 1] += e0a * v0.y;
            oa[i * 4 + 2] += e0a * v0.z;
            oa[i * 4 + 3] += e0a * v0.w;
            ob[i * 4]     += e0b * v0.x;
            ob[i * 4 + 1] += e0b * v0.y;
            ob[i * 4 + 2] += e0b * v0.z;
            ob[i * 4 + 3] += e0b * v0.w;
            oa[i * 4]     += e1a * v1.x;
            oa[i * 4 + 1] += e1a * v1.y;
            oa[i * 4 + 2] += e1a * v1.z;
            oa[i * 4 + 3] += e1a * v1.w;
            ob[i * 4]     += e1b * v1.x;
            ob[i * 4 + 1] += e1b * v1.y;
            ob[i * 4 + 2] += e1b * v1.z;
            ob[i * 4 + 3] += e1b * v1.w;
        }
    }

    // All warps must finish reading K before o-partials overwrite it.
    __syncthreads();

    // o-partials alias Ksm: warp w, local row rl -> sm[w*2048 + rl*32 + d]
    {
        float* Pa = sm + w * 2048 + lane * 32;
        float* Pb = sm + w * 2048 + (lane + 32) * 32;
#pragma unroll
        for (int i = 0; i < 8; i++) {
            ((float4*)Pa)[i] = make_float4(oa[4 * i], oa[4 * i + 1], oa[4 * i + 2], oa[4 * i + 3]);
            ((float4*)Pb)[i] = make_float4(ob[4 * i], ob[4 * i + 1], ob[4 * i + 2], ob[4 * i + 3]);
        }
        sArr[w * 64 + lane]      = sa;
        sArr[w * 64 + lane + 32] = sb;
    }
    __syncthreads();

    // Reduce 4 warp partials: o (2048 floats) and s (64).
    for (int i = tid; i < 2048; i += 128) {
        sm[i] = sm[i] + sm[2048 + i] + sm[4096 + i] + sm[6144 + i];
    }
    if (tid < 64) {
        float ssum = sArr[tid] + sArr[64 + tid] + sArr[128 + tid] + sArr[192 + tid];
        sArr[tid] = 1.f / ssum;
    }
    __syncthreads();

    // Normalize + write: 64 rows x 8 float4 = 512 stores / 128 threads.
    int b = bh >> 2, h = bh & 3;
    for (int i = tid; i < 512; i += 128) {
        int rr = i >> 3;
        int d0 = (i & 7) * 4;
        float inv = sArr[rr];
        const float* R = sm + rr * 32 + d0;
        float4 ov = make_float4(R[0] * inv, R[1] * inv, R[2] * inv, R[3] * inv);
        *(float4*)&g_o[(((b << 8) + 64 * t + rr) * 128) + h * 32 + d0] = ov;
    }
}

// ---------------------------------------------------------------------------
extern "C" void kernel_launch(void* const* d_in, const int* in_sizes, int n_in,
                              void* d_out, int out_size) {
    const float* x  = (const float*)d_in[0];
    const float* wq = (const float*)d_in[1];
    const float* wk = (const float*)d_in[2];
    const float* wv = (const float*)d_in[3];
    const float* wo = (const float*)d_in[4];
    const float* Aq = (const float*)d_in[5];
    const float* Bq = (const float*)d_in[6];
    const float* Ak = (const float*)d_in[7];
    const float* Bk = (const float*)d_in[8];
    const float* Av = (const float*)d_in[9];
    const float* Bv = (const float*)d_in[10];
    float* out = (float*)d_out;

    fuse_weights<<<512, 128>>>(wq, wk, wv, wo, Aq, Bq, Ak, Bk, Av, Bv);
    rope_table<<<1, 256>>>();

    qkv_gemm<<<dim3(256, 3), dim3(16, 16)>>>(x);

    int smem_attn = (16384 + 256) * (int)sizeof(float);   // 66560
    cudaFuncSetAttribute(attn_split2, cudaFuncAttributeMaxDynamicSharedMemorySize, smem_attn);
    attn_split2<<<dim3(4, 512), 128, smem_attn>>>();

    out_gemm<<<256, dim3(16, 16)>>>(out);
}

// round 14
// speedup vs baseline: 1.1343x; 1.0757x over previous
#include <cuda_runtime.h>
#include <cuda_bf16.h>
#include <math.h>

#define NROWS 32768          // B*S = 128*256
#define INV_SQRT_HD 0.17677669529663687f   // 1/sqrt(32)

// Scratch (allocation-free rule: __device__ globals)
__device__ float g_weff[128 * 512];   // fused weights [k][col]; col: 0-127 q, 128-255 k, 256-383 v, 384-511 wo
__device__ float g_q[NROWS * 128];    // [b][h][s][d]
__device__ float g_k[NROWS * 128];
__device__ float g_v[NROWS * 128];
__device__ float g_o[NROWS * 128];    // [b][s][h*32+d]
__device__ float2 g_rope[256 * 16];   // {cos, sin} per (s, pair)

// bf16 split operands for the OUT projection experiment
__device__ __nv_bfloat16 g_woh[128 * 128];  // wo [n][k] hi
__device__ __nv_bfloat16 g_wol[128 * 128];  // wo [n][k] lo
__device__ __nv_bfloat16 g_oh[NROWS * 128]; // attn output hi
__device__ __nv_bfloat16 g_ol[NROWS * 128]; // attn output lo

__device__ __forceinline__ void split_bf16(float v, __nv_bfloat16& hi, __nv_bfloat16& lo) {
    hi = __float2bfloat16_rn(v);
    lo = __float2bfloat16_rn(v - __bfloat162float(hi));
}

__device__ __forceinline__ void mma_bf16(float* c, const unsigned* a, const unsigned* b) {
    asm("mma.sync.aligned.m16n8k16.row.col.f32.bf16.bf16.f32 "
        "{%0,%1,%2,%3},{%4,%5,%6,%7},{%8,%9},{%0,%1,%2,%3};"
        : "+f"(c[0]), "+f"(c[1]), "+f"(c[2]), "+f"(c[3])
        : "r"(a[0]), "r"(a[1]), "r"(a[2]), "r"(a[3]), "r"(b[0]), "r"(b[1]));
}

// ---------------------------------------------------------------------------
// Kernel 0a: fold LoRA into effective weights (fp32), + bf16 hi/lo of wo.
// ---------------------------------------------------------------------------
__global__ void fuse_weights(const float* __restrict__ wq, const float* __restrict__ wk,
                             const float* __restrict__ wv, const float* __restrict__ wo,
                             const float* __restrict__ Aq, const float* __restrict__ Bq,
                             const float* __restrict__ Ak, const float* __restrict__ Bk,
                             const float* __restrict__ Av, const float* __restrict__ Bv) {
    int col = blockIdx.x;           // 0..511
    int j = threadIdx.x;            // 0..127
    int g = col >> 7;
    int i = col & 127;
    const float* w = (g == 0) ? wq : (g == 1) ? wk : (g == 2) ? wv : wo;
    float acc = w[i * 128 + j];
    if (g < 3) {
        const float* A  = (g == 0) ? Aq : (g == 1) ? Ak : Av;
        const float* Bm = (g == 0) ? Bq : (g == 1) ? Bk : Bv;
        float s = 0.f;
#pragma unroll
        for (int r = 0; r < 8; r++) s += Bm[i * 8 + r] * A[r * 128 + j];
        acc += 2.0f * s;            // SCALING = 16/8
    }
    g_weff[j * 512 + col] = acc;
    if (g == 3) {
        __nv_bfloat16 hi, lo;
        split_bf16(acc, hi, lo);
        g_woh[i * 128 + j] = hi;    // [n][k]
        g_wol[i * 128 + j] = lo;
    }
}

// ---------------------------------------------------------------------------
// Kernel 0b: RoPE cos/sin table
// ---------------------------------------------------------------------------
__global__ void rope_table() {
    int s = threadIdx.x;            // 0..255
#pragma unroll
    for (int p = 0; p < 16; p++) {
        float invf = powf(10000.0f, -(float)p / 16.0f);
        float ang = (float)s * invf;
        float sn, cs;
        sincosf(ang, &sn, &cs);
        g_rope[s * 16 + p] = make_float2(cs, sn);
    }
}

// ---------------------------------------------------------------------------
// Split kernel: g_o (device symbol, no cudaGetSymbolAddress) -> bf16 hi/lo
// ---------------------------------------------------------------------------
__global__ void split_o() {
    int idx = blockIdx.x * 256 + threadIdx.x;      // float4 index
    float4 v = ((const float4*)g_o)[idx];
    __nv_bfloat16 h0, h1, h2, h3, l0, l1, l2, l3;
    split_bf16(v.x, h0, l0);
    split_bf16(v.y, h1, l1);
    split_bf16(v.z, h2, l2);
    split_bf16(v.w, h3, l3);
    __nv_bfloat162* dh2 = (__nv_bfloat162*)g_oh;
    __nv_bfloat162* dl2 = (__nv_bfloat162*)g_ol;
    dh2[idx * 2]     = __nv_bfloat162(h0, h1);
    dh2[idx * 2 + 1] = __nv_bfloat162(h2, h3);
    dl2[idx * 2]     = __nv_bfloat162(l0, l1);
    dl2[idx * 2 + 1] = __nv_bfloat162(l2, l3);
}

// ---------------------------------------------------------------------------
// Shared scalar GEMM mainloop (round-8, used by qkv)
// ---------------------------------------------------------------------------
__device__ __forceinline__ void gemm128_body(const float* __restrict__ Asrc, int m0,
                                             const float* __restrict__ Bsrc,
                                             float acc[8][8],
                                             float (*As)[33], float (*Bs)[132]) {
    int tx = threadIdx.x, ty = threadIdx.y;
    int tid = ty * 16 + tx;

    for (int kt = 0; kt < 4; kt++) {
#pragma unroll
        for (int i = 0; i < 4; i++) {
            int idx = tid + i * 256;
            int r = idx >> 3, c4 = idx & 7;
            float4 v = *(const float4*)&Asrc[(m0 + r) * 128 + kt * 32 + c4 * 4];
            As[r][c4 * 4]     = v.x;
            As[r][c4 * 4 + 1] = v.y;
            As[r][c4 * 4 + 2] = v.z;
            As[r][c4 * 4 + 3] = v.w;
        }
#pragma unroll
        for (int i = 0; i < 4; i++) {
            int idx = tid + i * 256;
            int kr = idx >> 5, c4 = idx & 31;
            float4 v = *(const float4*)&Bsrc[(kt * 32 + kr) * 512 + c4 * 4];
            *(float4*)&Bs[kr][c4 * 4] = v;
        }
        __syncthreads();

#pragma unroll
        for (int kk = 0; kk < 32; kk++) {
            float a[8];
#pragma unroll
            for (int i = 0; i < 8; i++) a[i] = As[ty * 8 + i][kk];
            float4 b0 = *(const float4*)&Bs[kk][tx * 8];
            float4 b1 = *(const float4*)&Bs[kk][tx * 8 + 4];
            float bb[8] = {b0.x, b0.y, b0.z, b0.w, b1.x, b1.y, b1.z, b1.w};
#pragma unroll
            for (int i = 0; i < 8; i++)
#pragma unroll
                for (int j = 0; j < 8; j++) acc[i][j] += a[i] * bb[j];
        }
        __syncthreads();
    }
}

// ---------------------------------------------------------------------------
// Kernel 2: QKV projection + RoPE (round-8 scalar, unchanged)
// ---------------------------------------------------------------------------
__global__ __launch_bounds__(256, 2) void qkv_gemm(const float* __restrict__ X) {
    __shared__ float As[128][33];
    __shared__ float Bs[32][132];
    float acc[8][8] = {};

    int m0 = blockIdx.x * 128;
    int g = blockIdx.y;                 // 0=q, 1=k, 2=v
    gemm128_body(X, m0, g_weff + g * 128, acc, As, Bs);

    int tx = threadIdx.x, ty = threadIdx.y;
    float* dst = (g == 0) ? g_q : (g == 1) ? g_k : g_v;

#pragma unroll
    for (int i = 0; i < 8; i++) {
        int row = m0 + ty * 8 + i;
        int b = row >> 8, s = row & 255;
        if (g < 2) {
#pragma unroll
            for (int u = 0; u < 4; u++) {
                int col = tx * 8 + 2 * u;
                int h = col >> 5, d = col & 31;
                int p = d >> 1;
                float2 cs = g_rope[s * 16 + p];
                float x1 = acc[i][2 * u], x2 = acc[i][2 * u + 1];
                float2 o = make_float2(x1 * cs.x - x2 * cs.y,
                                       x1 * cs.y + x2 * cs.x);
                *(float2*)&dst[(((b << 2) + h) * 256 + s) * 32 + d] = o;
            }
        } else {
            int col = tx * 8;
            int h = col >> 5, d = col & 31;
            float* dp = &dst[(((b << 2) + h) * 256 + s) * 32 + d];
            *(float4*)dp       = make_float4(acc[i][0], acc[i][1], acc[i][2], acc[i][3]);
            *(float4*)(dp + 4) = make_float4(acc[i][4], acc[i][5], acc[i][6], acc[i][7]);
        }
    }
}

// ---------------------------------------------------------------------------
// Kernel 4 (EXPERIMENT): output projection via bf16 3-pass MMA.
// CTA 128x128, 8 warps (2Mx4N), warp tile 64x32, BK=32.
// Shared tiles EXPLICITLY 16-byte aligned (row stride 80B keeps rows aligned).
// ---------------------------------------------------------------------------
__global__ __launch_bounds__(256, 2) void out_mma(float* __restrict__ out) {
    __shared__ __align__(16) __nv_bfloat16 Ah[128][40];
    __shared__ __align__(16) __nv_bfloat16 Al[128][40];
    __shared__ __align__(16) __nv_bfloat16 Bh[128][40];
    __shared__ __align__(16) __nv_bfloat16 Bl[128][40];
    float acc[4][4][4] = {};

    int tid = threadIdx.x;
    int lane = tid & 31, warp = tid >> 5;
    int warpM = warp >> 2, warpN = warp & 3;
    int g = lane >> 2, tg = lane & 3;
    int m0 = blockIdx.x * 128;

    for (int kt = 0; kt < 4; kt++) {
#pragma unroll
        for (int i = 0; i < 2; i++) {
            int idx = tid + i * 256;
            int r = idx >> 2, c = idx & 3;
            int goff = r * 128 + kt * 32 + c * 8;
            *(uint4*)&Ah[r][c * 8] = *(const uint4*)&g_oh[m0 * 128 + goff];
            *(uint4*)&Al[r][c * 8] = *(const uint4*)&g_ol[m0 * 128 + goff];
            *(uint4*)&Bh[r][c * 8] = *(const uint4*)&g_woh[goff];
            *(uint4*)&Bl[r][c * 8] = *(const uint4*)&g_wol[goff];
        }
        __syncthreads();

#pragma unroll
        for (int ks = 0; ks < 32; ks += 16) {
            unsigned bh[4][2], bl[4][2];
#pragma unroll
            for (int nt = 0; nt < 4; nt++) {
                int n = warpN * 32 + nt * 8 + g;
                bh[nt][0] = *(const unsigned*)&Bh[n][ks + 2 * tg];
                bh[nt][1] = *(const unsigned*)&Bh[n][ks + 2 * tg + 8];
                bl[nt][0] = *(const unsigned*)&Bl[n][ks + 2 * tg];
                bl[nt][1] = *(const unsigned*)&Bl[n][ks + 2 * tg + 8];
            }
#pragma unroll
            for (int mt = 0; mt < 4; mt++) {
                int r0 = warpM * 64 + mt * 16 + g;
                unsigned ah[4], al[4];
                ah[0] = *(const unsigned*)&Ah[r0][ks + 2 * tg];
                ah[1] = *(const unsigned*)&Ah[r0 + 8][ks + 2 * tg];
                ah[2] = *(const unsigned*)&Ah[r0][ks + 2 * tg + 8];
                ah[3] = *(const unsigned*)&Ah[r0 + 8][ks + 2 * tg + 8];
                al[0] = *(const unsigned*)&Al[r0][ks + 2 * tg];
                al[1] = *(const unsigned*)&Al[r0 + 8][ks + 2 * tg];
                al[2] = *(const unsigned*)&Al[r0][ks + 2 * tg + 8];
                al[3] = *(const unsigned*)&Al[r0 + 8][ks + 2 * tg + 8];
#pragma unroll
                for (int nt = 0; nt < 4; nt++) {
                    mma_bf16(acc[mt][nt], ah, bh[nt]);   // hi*hi
                    mma_bf16(acc[mt][nt], al, bh[nt]);   // lo*hi
                    mma_bf16(acc[mt][nt], ah, bl[nt]);   // hi*lo
                }
            }
        }
        __syncthreads();
    }

#pragma unroll
    for (int mt = 0; mt < 4; mt++) {
        int row0 = m0 + warpM * 64 + mt * 16 + g;
        int row1 = row0 + 8;
#pragma unroll
        for (int nt = 0; nt < 4; nt++) {
            int col = warpN * 32 + nt * 8 + 2 * tg;
            *(float2*)&out[row0 * 128 + col] = make_float2(acc[mt][nt][0], acc[mt][nt][1]);
            *(float2*)&out[row1 * 128 + col] = make_float2(acc[mt][nt][2], acc[mt][nt][3]);
        }
    }
}

// ---------------------------------------------------------------------------
// Kernel 3: split-K causal attention (round-8 verbatim)
// ---------------------------------------------------------------------------
__global__ __launch_bounds__(128, 2) void attn_split2() {
    extern __shared__ float sm[];
    float* Ksm = sm;
    float* Vsm = sm + 8192;
    float* Psm = sm + 16384;

    int t  = blockIdx.x;
    int bh = blockIdx.y;
    int kmax = 64 * (t + 1);
    const float* Qb = g_q + bh * 8192;
    const float4* Kb4 = (const float4*)(g_k + bh * 8192);
    const float4* Vb4 = (const float4*)(g_v + bh * 8192);
    int tid = threadIdx.x;

    int n4 = kmax * 8;
    for (int i = tid; i < n4; i += 128) {
        ((float4*)Ksm)[i] = Kb4[i];
        ((float4*)Vsm)[i] = Vb4[i];
    }
    __syncthreads();

    int w = tid >> 5, lane = tid & 31;
    int ra = 64 * t + lane;
    int rb = ra + 32;

    float qa[32], qb[32];
    const float4* Qa4 = (const float4*)(Qb + ra * 32);
    const float4* Qb4r = (const float4*)(Qb + rb * 32);
#pragma unroll
    for (int i = 0; i < 8; i++) {
        float4 va = Qa4[i], vb = Qb4r[i];
        qa[i * 4]     = va.x * INV_SQRT_HD; qa[i * 4 + 1] = va.y * INV_SQRT_HD;
        qa[i * 4 + 2] = va.z * INV_SQRT_HD; qa[i * 4 + 3] = va.w * INV_SQRT_HD;
        qb[i * 4]     = vb.x * INV_SQRT_HD; qb[i * 4 + 1] = vb.y * INV_SQRT_HD;
        qb[i * 4 + 2] = vb.z * INV_SQRT_HD; qb[i * 4 + 3] = vb.w * INV_SQRT_HD;
    }

    float oa[32], ob[32];
#pragma unroll
    for (int d = 0; d < 32; d++) { oa[d] = 0.f; ob[d] = 0.f; }
    float sa = 0.f, sb = 0.f;

    int C = 16 * (t + 1);
    int k0 = w * C;
    int k1 = k0 + C;
    for (int k = k0; k < k1; k++) {
        const float4* Kr = (const float4*)(Ksm + k * 32);
        float da0 = 0.f, da1 = 0.f, db0 = 0.f, db1 = 0.f;
#pragma unroll
        for (int i = 0; i < 8; i++) {
            float4 kv = Kr[i];
            da0 += qa[i * 4]     * kv.x;
            da1 += qa[i * 4 + 1] * kv.y;
            da0 += qa[i * 4 + 2] * kv.z;
            da1 += qa[i * 4 + 3] * kv.w;
            db0 += qb[i * 4]     * kv.x;
            db1 += qb[i * 4 + 1] * kv.y;
            db0 += qb[i * 4 + 2] * kv.z;
            db1 += qb[i * 4 + 3] * kv.w;
        }
        float siga = (k <= ra) ? (da0 + da1) : -INFINITY;
        float sigb = (k <= rb) ? (db0 + db1) : -INFINITY;
        float ea = __expf(siga);
        float eb = __expf(sigb);
        sa += ea; sb += eb;
        const float4* Vr = (const float4*)(Vsm + k * 32);
#pragma unroll
        for (int i = 0; i < 8; i++) {
            float4 vv = Vr[i];
            oa[i * 4]     += ea * vv.x;
            oa[i * 4 + 1] += ea * vv.y;
            oa[i * 4 + 2] += ea * vv.z;
            oa[i * 4 + 3] += ea * vv.w;
            ob[i * 4]     += eb * vv.x;
            ob[i * 4 + 1] += eb * vv.y;
            ob[i * 4 + 2] += eb * vv.z;
            ob[i * 4 + 3] += eb * vv.w;
        }
    }

    float* Pa = Psm + w * 2112 + lane * 33;
    float* Pb = Pa + 32 * 33;
    Pa[0] = sa;
    Pb[0] = sb;
#pragma unroll
    for (int d = 0; d < 32; d++) { Pa[1 + d] = oa[d]; Pb[1 + d] = ob[d]; }
    __syncthreads();

    for (int i = tid; i < 2112; i += 128) {
        float acc = Psm[i] + Psm[2112 + i] + Psm[4224 + i] + Psm[6336 + i];
        Psm[i] = acc;
    }
    __syncthreads();

    int b = bh >> 2, h = bh & 3;
    for (int i = tid; i < 512; i += 128) {
        int rr = i >> 3;
        int d0 = (i & 7) * 4;
        float inv = 1.f / Psm[rr * 33];
        float* R = &Psm[rr * 33 + 1 + d0];
        float4 ov = make_float4(R[0] * inv, R[1] * inv, R[2] * inv, R[3] * inv);
        *(float4*)&g_o[(((b << 8) + 64 * t + rr) * 128) + h * 32 + d0] = ov;
    }
}

// ---------------------------------------------------------------------------
extern "C" void kernel_launch(void* const* d_in, const int* in_sizes, int n_in,
                              void* d_out, int out_size) {
    const float* x  = (const float*)d_in[0];
    const float* wq = (const float*)d_in[1];
    const float* wk = (const float*)d_in[2];
    const float* wv = (const float*)d_in[3];
    const float* wo = (const float*)d_in[4];
    const float* Aq = (const float*)d_in[5];
    const float* Bq = (const float*)d_in[6];
    const float* Ak = (const float*)d_in[7];
    const float* Bk = (const float*)d_in[8];
    const float* Av = (const float*)d_in[9];
    const float* Bv = (const float*)d_in[10];
    float* out = (float*)d_out;

    fuse_weights<<<512, 128>>>(wq, wk, wv, wo, Aq, Bq, Ak, Bk, Av, Bv);
    rope_table<<<1, 256>>>();

    qkv_gemm<<<dim3(256, 3), dim3(16, 16)>>>(x);

    int smem_attn = (16384 + 8448) * (int)sizeof(float);   // 99328
    cudaFuncSetAttribute(attn_split2, cudaFuncAttributeMaxDynamicSharedMemorySize, smem_attn);
    attn_split2<<<dim3(4, 512), 128, smem_attn>>>();

    // Split attention output to bf16 hi/lo (device symbol, no pointer query),
    // then MMA output projection.
    split_o<<<NROWS * 128 / 4 / 256, 256>>>();
    out_mma<<<256, 256>>>(out);
}

// round 15
// speedup vs baseline: 1.3734x; 1.2108x over previous
#include <cuda_runtime.h>
#include <cuda_bf16.h>
#include <math.h>

#define NROWS 32768          // B*S = 128*256
#define INV_SQRT_HD 0.17677669529663687f   // 1/sqrt(32)

// Scratch (allocation-free rule: __device__ globals)
__device__ float g_q[NROWS * 128];    // [b][h][s][d]
__device__ float g_k[NROWS * 128];
__device__ float g_v[NROWS * 128];
__device__ float g_o[NROWS * 128];    // [b][s][h*32+d]
__device__ float2 g_rope[256 * 16];   // {cos, sin} per (s, pair)

// bf16 split operands (x ≈ hi + lo to ~2^-17 relative)
__device__ __nv_bfloat16 g_wh[512 * 128];   // fused weights [n][k]: 0-127 q, 128-255 k, 256-383 v, 384-511 wo
__device__ __nv_bfloat16 g_wl[512 * 128];
__device__ __nv_bfloat16 g_xh[NROWS * 128]; // input x
__device__ __nv_bfloat16 g_xl[NROWS * 128];
__device__ __nv_bfloat16 g_oh[NROWS * 128]; // attn output
__device__ __nv_bfloat16 g_ol[NROWS * 128];

__device__ __forceinline__ void split_bf16(float v, __nv_bfloat16& hi, __nv_bfloat16& lo) {
    hi = __float2bfloat16_rn(v);
    lo = __float2bfloat16_rn(v - __bfloat162float(hi));
}

__device__ __forceinline__ void mma_bf16(float* c, const unsigned* a, const unsigned* b) {
    asm("mma.sync.aligned.m16n8k16.row.col.f32.bf16.bf16.f32 "
        "{%0,%1,%2,%3},{%4,%5,%6,%7},{%8,%9},{%0,%1,%2,%3};"
        : "+f"(c[0]), "+f"(c[1]), "+f"(c[2]), "+f"(c[3])
        : "r"(a[0]), "r"(a[1]), "r"(a[2]), "r"(a[3]), "r"(b[0]), "r"(b[1]));
}

// ---------------------------------------------------------------------------
// Kernel 0a: fold LoRA into effective weights; emit bf16 hi/lo [n][k].
// ---------------------------------------------------------------------------
__global__ void fuse_weights(const float* __restrict__ wq, const float* __restrict__ wk,
                             const float* __restrict__ wv, const float* __restrict__ wo,
                             const float* __restrict__ Aq, const float* __restrict__ Bq,
                             const float* __restrict__ Ak, const float* __restrict__ Bk,
                             const float* __restrict__ Av, const float* __restrict__ Bv) {
    int col = blockIdx.x;           // n: 0..511
    int j = threadIdx.x;            // k: 0..127
    int g = col >> 7;
    int i = col & 127;
    const float* w = (g == 0) ? wq : (g == 1) ? wk : (g == 2) ? wv : wo;
    float acc = w[i * 128 + j];
    if (g < 3) {
        const float* A  = (g == 0) ? Aq : (g == 1) ? Ak : Av;
        const float* Bm = (g == 0) ? Bq : (g == 1) ? Bk : Bv;
        float s = 0.f;
#pragma unroll
        for (int r = 0; r < 8; r++) s += Bm[i * 8 + r] * A[r * 128 + j];
        acc += 2.0f * s;            // SCALING = 16/8
    }
    __nv_bfloat16 hi, lo;
    split_bf16(acc, hi, lo);
    g_wh[col * 128 + j] = hi;
    g_wl[col * 128 + j] = lo;
}

// ---------------------------------------------------------------------------
// Kernel 0b: RoPE cos/sin table
// ---------------------------------------------------------------------------
__global__ void rope_table() {
    int s = threadIdx.x;            // 0..255
#pragma unroll
    for (int p = 0; p < 16; p++) {
        float invf = powf(10000.0f, -(float)p / 16.0f);
        float ang = (float)s * invf;
        float sn, cs;
        sincosf(ang, &sn, &cs);
        g_rope[s * 16 + p] = make_float2(cs, sn);
    }
}

// ---------------------------------------------------------------------------
// Split kernels: fp32 -> bf16 hi/lo (validated structure)
// ---------------------------------------------------------------------------
__global__ void split_x(const float* __restrict__ src) {
    int idx = blockIdx.x * 256 + threadIdx.x;      // float4 index
    float4 v = ((const float4*)src)[idx];
    __nv_bfloat16 h0, h1, h2, h3, l0, l1, l2, l3;
    split_bf16(v.x, h0, l0);
    split_bf16(v.y, h1, l1);
    split_bf16(v.z, h2, l2);
    split_bf16(v.w, h3, l3);
    __nv_bfloat162* dh2 = (__nv_bfloat162*)g_xh;
    __nv_bfloat162* dl2 = (__nv_bfloat162*)g_xl;
    dh2[idx * 2]     = __nv_bfloat162(h0, h1);
    dh2[idx * 2 + 1] = __nv_bfloat162(h2, h3);
    dl2[idx * 2]     = __nv_bfloat162(l0, l1);
    dl2[idx * 2 + 1] = __nv_bfloat162(l2, l3);
}

__global__ void split_o() {
    int idx = blockIdx.x * 256 + threadIdx.x;      // float4 index
    float4 v = ((const float4*)g_o)[idx];
    __nv_bfloat16 h0, h1, h2, h3, l0, l1, l2, l3;
    split_bf16(v.x, h0, l0);
    split_bf16(v.y, h1, l1);
    split_bf16(v.z, h2, l2);
    split_bf16(v.w, h3, l3);
    __nv_bfloat162* dh2 = (__nv_bfloat162*)g_oh;
    __nv_bfloat162* dl2 = (__nv_bfloat162*)g_ol;
    dh2[idx * 2]     = __nv_bfloat162(h0, h1);
    dh2[idx * 2 + 1] = __nv_bfloat162(h2, h3);
    dl2[idx * 2]     = __nv_bfloat162(l0, l1);
    dl2[idx * 2 + 1] = __nv_bfloat162(l2, l3);
}

// ---------------------------------------------------------------------------
// Validated bf16 3-pass MMA GEMM body (round-14 out_mma structure).
// CTA 128x128, 8 warps (2Mx4N), warp tile 64x32, BK=32, tiles stride 40.
// acc[mt][nt][4]: D rows (g, g+8), cols (2tg, 2tg+1).
// ---------------------------------------------------------------------------
#define MMA_GEMM_BODY(Ahg, Alg, Bhg, Blg)                                          \
    for (int kt = 0; kt < 4; kt++) {                                               \
        _Pragma("unroll")                                                          \
        for (int i = 0; i < 2; i++) {                                              \
            int idx = tid + i * 256;                                               \
            int r = idx >> 2, c = idx & 3;                                         \
            int goff = r * 128 + kt * 32 + c * 8;                                  \
            *(uint4*)&Ah[r][c * 8] = *(const uint4*)&(Ahg)[m0 * 128 + goff];       \
            *(uint4*)&Al[r][c * 8] = *(const uint4*)&(Alg)[m0 * 128 + goff];       \
            *(uint4*)&Bh[r][c * 8] = *(const uint4*)&(Bhg)[goff];                  \
            *(uint4*)&Bl[r][c * 8] = *(const uint4*)&(Blg)[goff];                  \
        }                                                                          \
        __syncthreads();                                                           \
        _Pragma("unroll")                                                          \
        for (int ks = 0; ks < 32; ks += 16) {                                      \
            unsigned bh[4][2], bl[4][2];                                           \
            _Pragma("unroll")                                                      \
            for (int nt = 0; nt < 4; nt++) {                                       \
                int n = warpN * 32 + nt * 8 + g;                                   \
                bh[nt][0] = *(const unsigned*)&Bh[n][ks + 2 * tg];                 \
                bh[nt][1] = *(const unsigned*)&Bh[n][ks + 2 * tg + 8];             \
                bl[nt][0] = *(const unsigned*)&Bl[n][ks + 2 * tg];                 \
                bl[nt][1] = *(const unsigned*)&Bl[n][ks + 2 * tg + 8];             \
            }                                                                      \
            _Pragma("unroll")                                                      \
            for (int mt = 0; mt < 4; mt++) {                                       \
                int r0 = warpM * 64 + mt * 16 + g;                                 \
                unsigned ah[4], al[4];                                             \
                ah[0] = *(const unsigned*)&Ah[r0][ks + 2 * tg];                    \
                ah[1] = *(const unsigned*)&Ah[r0 + 8][ks + 2 * tg];                \
                ah[2] = *(const unsigned*)&Ah[r0][ks + 2 * tg + 8];                \
                ah[3] = *(const unsigned*)&Ah[r0 + 8][ks + 2 * tg + 8];            \
                al[0] = *(const unsigned*)&Al[r0][ks + 2 * tg];                    \
                al[1] = *(const unsigned*)&Al[r0 + 8][ks + 2 * tg];                \
                al[2] = *(const unsigned*)&Al[r0][ks + 2 * tg + 8];                \
                al[3] = *(const unsigned*)&Al[r0 + 8][ks + 2 * tg + 8];            \
                _Pragma("unroll")                                                  \
                for (int nt = 0; nt < 4; nt++) {                                   \
                    mma_bf16(acc[mt][nt], ah, bh[nt]);                             \
                    mma_bf16(acc[mt][nt], al, bh[nt]);                             \
                    mma_bf16(acc[mt][nt], ah, bl[nt]);                             \
                }                                                                  \
            }                                                                      \
        }                                                                          \
        __syncthreads();                                                           \
    }

// ---------------------------------------------------------------------------
// Kernel 2: QKV projection via bf16 MMA + RoPE epilogue + scatter.
// ---------------------------------------------------------------------------
__global__ __launch_bounds__(256, 2) void qkv_mma() {
    __shared__ __align__(16) __nv_bfloat16 Ah[128][40];
    __shared__ __align__(16) __nv_bfloat16 Al[128][40];
    __shared__ __align__(16) __nv_bfloat16 Bh[128][40];
    __shared__ __align__(16) __nv_bfloat16 Bl[128][40];
    float acc[4][4][4] = {};

    int tid = threadIdx.x;
    int lane = tid & 31, warp = tid >> 5;
    int warpM = warp >> 2, warpN = warp & 3;
    int g = lane >> 2, tg = lane & 3;
    int m0 = blockIdx.x * 128;
    int gsel = blockIdx.y;              // 0=q, 1=k, 2=v
    const __nv_bfloat16* Bhg = g_wh + gsel * 128 * 128;
    const __nv_bfloat16* Blg = g_wl + gsel * 128 * 128;

    MMA_GEMM_BODY(g_xh, g_xl, Bhg, Blg)

    float* dst = (gsel == 0) ? g_q : (gsel == 1) ? g_k : g_v;

#pragma unroll
    for (int mt = 0; mt < 4; mt++) {
        int row0 = m0 + warpM * 64 + mt * 16 + g;
        int row1 = row0 + 8;
        int b = row0 >> 8;
        int s0 = row0 & 255, s1 = row1 & 255;
#pragma unroll
        for (int nt = 0; nt < 4; nt++) {
            int col = warpN * 32 + nt * 8 + 2 * tg;   // even, 0..126
            int h = col >> 5, d = col & 31;
            float c0 = acc[mt][nt][0], c1 = acc[mt][nt][1];
            float c2 = acc[mt][nt][2], c3 = acc[mt][nt][3];
            if (gsel < 2) {
                int p = d >> 1;
                float2 csA = g_rope[s0 * 16 + p];
                float2 csB = g_rope[s1 * 16 + p];
                float y0 = c0 * csA.x - c1 * csA.y;
                float y1 = c0 * csA.y + c1 * csA.x;
                float y2 = c2 * csB.x - c3 * csB.y;
                float y3 = c2 * csB.y + c3 * csB.x;
                c0 = y0; c1 = y1; c2 = y2; c3 = y3;
            }
            int base = ((b << 2) + h) * 256;
            *(float2*)&dst[(base + s0) * 32 + d] = make_float2(c0, c1);
            *(float2*)&dst[(base + s1) * 32 + d] = make_float2(c2, c3);
        }
    }
}

// ---------------------------------------------------------------------------
// Kernel 4: output projection via bf16 MMA (round-14 validated, verbatim)
// ---------------------------------------------------------------------------
__global__ __launch_bounds__(256, 2) void out_mma(float* __restrict__ out) {
    __shared__ __align__(16) __nv_bfloat16 Ah[128][40];
    __shared__ __align__(16) __nv_bfloat16 Al[128][40];
    __shared__ __align__(16) __nv_bfloat16 Bh[128][40];
    __shared__ __align__(16) __nv_bfloat16 Bl[128][40];
    float acc[4][4][4] = {};

    int tid = threadIdx.x;
    int lane = tid & 31, warp = tid >> 5;
    int warpM = warp >> 2, warpN = warp & 3;
    int g = lane >> 2, tg = lane & 3;
    int m0 = blockIdx.x * 128;
    const __nv_bfloat16* Bhg = g_wh + 384 * 128;
    const __nv_bfloat16* Blg = g_wl + 384 * 128;

    MMA_GEMM_BODY(g_oh, g_ol, Bhg, Blg)

#pragma unroll
    for (int mt = 0; mt < 4; mt++) {
        int row0 = m0 + warpM * 64 + mt * 16 + g;
        int row1 = row0 + 8;
#pragma unroll
        for (int nt = 0; nt < 4; nt++) {
            int col = warpN * 32 + nt * 8 + 2 * tg;
            *(float2*)&out[row0 * 128 + col] = make_float2(acc[mt][nt][0], acc[mt][nt][1]);
            *(float2*)&out[row1 * 128 + col] = make_float2(acc[mt][nt][2], acc[mt][nt][3]);
        }
    }
}

// ---------------------------------------------------------------------------
// Kernel 3: split-K causal attention (round-8 verbatim)
// ---------------------------------------------------------------------------
__global__ __launch_bounds__(128, 2) void attn_split2() {
    extern __shared__ float sm[];
    float* Ksm = sm;
    float* Vsm = sm + 8192;
    float* Psm = sm + 16384;

    int t  = blockIdx.x;
    int bh = blockIdx.y;
    int kmax = 64 * (t + 1);
    const float* Qb = g_q + bh * 8192;
    const float4* Kb4 = (const float4*)(g_k + bh * 8192);
    const float4* Vb4 = (const float4*)(g_v + bh * 8192);
    int tid = threadIdx.x;

    int n4 = kmax * 8;
    for (int i = tid; i < n4; i += 128) {
        ((float4*)Ksm)[i] = Kb4[i];
        ((float4*)Vsm)[i] = Vb4[i];
    }
    __syncthreads();

    int w = tid >> 5, lane = tid & 31;
    int ra = 64 * t + lane;
    int rb = ra + 32;

    float qa[32], qb[32];
    const float4* Qa4 = (const float4*)(Qb + ra * 32);
    const float4* Qb4r = (const float4*)(Qb + rb * 32);
#pragma unroll
    for (int i = 0; i < 8; i++) {
        float4 va = Qa4[i], vb = Qb4r[i];
        qa[i * 4]     = va.x * INV_SQRT_HD; qa[i * 4 + 1] = va.y * INV_SQRT_HD;
        qa[i * 4 + 2] = va.z * INV_SQRT_HD; qa[i * 4 + 3] = va.w * INV_SQRT_HD;
        qb[i * 4]     = vb.x * INV_SQRT_HD; qb[i * 4 + 1] = vb.y * INV_SQRT_HD;
        qb[i * 4 + 2] = vb.z * INV_SQRT_HD; qb[i * 4 + 3] = vb.w * INV_SQRT_HD;
    }

    float oa[32], ob[32];
#pragma unroll
    for (int d = 0; d < 32; d++) { oa[d] = 0.f; ob[d] = 0.f; }
    float sa = 0.f, sb = 0.f;

    int C = 16 * (t + 1);
    int k0 = w * C;
    int k1 = k0 + C;
    for (int k = k0; k < k1; k++) {
        const float4* Kr = (const float4*)(Ksm + k * 32);
        float da0 = 0.f, da1 = 0.f, db0 = 0.f, db1 = 0.f;
#pragma unroll
        for (int i = 0; i < 8; i++) {
            float4 kv = Kr[i];
            da0 += qa[i * 4]     * kv.x;
            da1 += qa[i * 4 + 1] * kv.y;
            da0 += qa[i * 4 + 2] * kv.z;
            da1 += qa[i * 4 + 3] * kv.w;
            db0 += qb[i * 4]     * kv.x;
            db1 += qb[i * 4 + 1] * kv.y;
            db0 += qb[i * 4 + 2] * kv.z;
            db1 += qb[i * 4 + 3] * kv.w;
        }
        float siga = (k <= ra) ? (da0 + da1) : -INFINITY;
        float sigb = (k <= rb) ? (db0 + db1) : -INFINITY;
        float ea = __expf(siga);
        float eb = __expf(sigb);
        sa += ea; sb += eb;
        const float4* Vr = (const float4*)(Vsm + k * 32);
#pragma unroll
        for (int i = 0; i < 8; i++) {
            float4 vv = Vr[i];
            oa[i * 4]     += ea * vv.x;
            oa[i * 4 + 1] += ea * vv.y;
            oa[i * 4 + 2] += ea * vv.z;
            oa[i * 4 + 3] += ea * vv.w;
            ob[i * 4]     += eb * vv.x;
            ob[i * 4 + 1] += eb * vv.y;
            ob[i * 4 + 2] += eb * vv.z;
            ob[i * 4 + 3] += eb * vv.w;
        }
    }

    float* Pa = Psm + w * 2112 + lane * 33;
    float* Pb = Pa + 32 * 33;
    Pa[0] = sa;
    Pb[0] = sb;
#pragma unroll
    for (int d = 0; d < 32; d++) { Pa[1 + d] = oa[d]; Pb[1 + d] = ob[d]; }
    __syncthreads();

    for (int i = tid; i < 2112; i += 128) {
        float acc = Psm[i] + Psm[2112 + i] + Psm[4224 + i] + Psm[6336 + i];
        Psm[i] = acc;
    }
    __syncthreads();

    int b = bh >> 2, h = bh & 3;
    for (int i = tid; i < 512; i += 128) {
        int rr = i >> 3;
        int d0 = (i & 7) * 4;
        float inv = 1.f / Psm[rr * 33];
        float* R = &Psm[rr * 33 + 1 + d0];
        float4 ov = make_float4(R[0] * inv, R[1] * inv, R[2] * inv, R[3] * inv);
        *(float4*)&g_o[(((b << 8) + 64 * t + rr) * 128) + h * 32 + d0] = ov;
    }
}

// ---------------------------------------------------------------------------
extern "C" void kernel_launch(void* const* d_in, const int* in_sizes, int n_in,
                              void* d_out, int out_size) {
    const float* x  = (const float*)d_in[0];
    const float* wq = (const float*)d_in[1];
    const float* wk = (const float*)d_in[2];
    const float* wv = (const float*)d_in[3];
    const float* wo = (const float*)d_in[4];
    const float* Aq = (const float*)d_in[5];
    const float* Bq = (const float*)d_in[6];
    const float* Ak = (const float*)d_in[7];
    const float* Bk = (const float*)d_in[8];
    const float* Av = (const float*)d_in[9];
    const float* Bv = (const float*)d_in[10];
    float* out = (float*)d_out;

    fuse_weights<<<512, 128>>>(wq, wk, wv, wo, Aq, Bq, Ak, Bk, Av, Bv);
    rope_table<<<1, 256>>>();

    // QKV projection on tensor cores
    split_x<<<NROWS * 128 / 4 / 256, 256>>>(x);
    qkv_mma<<<dim3(256, 3), 256>>>();

    // Attention (round-8 config)
    int smem_attn = (16384 + 8448) * (int)sizeof(float);   // 99328
    cudaFuncSetAttribute(attn_split2, cudaFuncAttributeMaxDynamicSharedMemorySize, smem_attn);
    attn_split2<<<dim3(4, 512), 128, smem_attn>>>();

    // Output projection on tensor cores
    split_o<<<NROWS * 128 / 4 / 256, 256>>>();
    out_mma<<<256, 256>>>(out);
}

// round 16
// speedup vs baseline: 1.4572x; 1.0610x over previous
#include <cuda_runtime.h>
#include <cuda_bf16.h>
#include <math.h>

#define NROWS 32768          // B*S = 128*256
#define INV_SQRT_HD 0.17677669529663687f   // 1/sqrt(32)

// Scratch (allocation-free rule: __device__ globals)
__device__ float g_q[NROWS * 128];    // [b][h][s][d]
__device__ float g_k[NROWS * 128];
__device__ float g_v[NROWS * 128];
__device__ float2 g_rope[256 * 16];   // {cos, sin} per (s, pair)

// bf16 split operands (x ≈ hi + lo to ~2^-17 relative)
__device__ __nv_bfloat16 g_wh[512 * 128];   // fused weights [n][k]: 0-127 q, 128-255 k, 256-383 v, 384-511 wo
__device__ __nv_bfloat16 g_wl[512 * 128];
__device__ __nv_bfloat16 g_xh[NROWS * 128]; // input x
__device__ __nv_bfloat16 g_xl[NROWS * 128];
__device__ __nv_bfloat16 g_oh[NROWS * 128]; // attn output (written by attn epilogue)
__device__ __nv_bfloat16 g_ol[NROWS * 128];

__device__ __forceinline__ void split_bf16(float v, __nv_bfloat16& hi, __nv_bfloat16& lo) {
    hi = __float2bfloat16_rn(v);
    lo = __float2bfloat16_rn(v - __bfloat162float(hi));
}

__device__ __forceinline__ void mma_bf16(float* c, const unsigned* a, const unsigned* b) {
    asm("mma.sync.aligned.m16n8k16.row.col.f32.bf16.bf16.f32 "
        "{%0,%1,%2,%3},{%4,%5,%6,%7},{%8,%9},{%0,%1,%2,%3};"
        : "+f"(c[0]), "+f"(c[1]), "+f"(c[2]), "+f"(c[3])
        : "r"(a[0]), "r"(a[1]), "r"(a[2]), "r"(a[3]), "r"(b[0]), "r"(b[1]));
}

__device__ __forceinline__ void cp16(unsigned dst, const void* src) {
    asm volatile("cp.async.cg.shared.global [%0], [%1], 16;" :: "r"(dst), "l"(src));
}

// ---------------------------------------------------------------------------
// Kernel 0a: fold LoRA into effective weights; emit bf16 hi/lo [n][k].
// ---------------------------------------------------------------------------
__global__ void fuse_weights(const float* __restrict__ wq, const float* __restrict__ wk,
                             const float* __restrict__ wv, const float* __restrict__ wo,
                             const float* __restrict__ Aq, const float* __restrict__ Bq,
                             const float* __restrict__ Ak, const float* __restrict__ Bk,
                             const float* __restrict__ Av, const float* __restrict__ Bv) {
    int col = blockIdx.x;           // n: 0..511
    int j = threadIdx.x;            // k: 0..127
    int g = col >> 7;
    int i = col & 127;
    const float* w = (g == 0) ? wq : (g == 1) ? wk : (g == 2) ? wv : wo;
    float acc = w[i * 128 + j];
    if (g < 3) {
        const float* A  = (g == 0) ? Aq : (g == 1) ? Ak : Av;
        const float* Bm = (g == 0) ? Bq : (g == 1) ? Bk : Bv;
        float s = 0.f;
#pragma unroll
        for (int r = 0; r < 8; r++) s += Bm[i * 8 + r] * A[r * 128 + j];
        acc += 2.0f * s;            // SCALING = 16/8
    }
    __nv_bfloat16 hi, lo;
    split_bf16(acc, hi, lo);
    g_wh[col * 128 + j] = hi;
    g_wl[col * 128 + j] = lo;
}

// ---------------------------------------------------------------------------
// Kernel 0b: RoPE cos/sin table
// ---------------------------------------------------------------------------
__global__ void rope_table() {
    int s = threadIdx.x;            // 0..255
#pragma unroll
    for (int p = 0; p < 16; p++) {
        float invf = powf(10000.0f, -(float)p / 16.0f);
        float ang = (float)s * invf;
        float sn, cs;
        sincosf(ang, &sn, &cs);
        g_rope[s * 16 + p] = make_float2(cs, sn);
    }
}

// ---------------------------------------------------------------------------
// split_x: fp32 -> bf16 hi/lo (validated)
// ---------------------------------------------------------------------------
__global__ void split_x(const float* __restrict__ src) {
    int idx = blockIdx.x * 256 + threadIdx.x;      // float4 index
    float4 v = ((const float4*)src)[idx];
    __nv_bfloat16 h0, h1, h2, h3, l0, l1, l2, l3;
    split_bf16(v.x, h0, l0);
    split_bf16(v.y, h1, l1);
    split_bf16(v.z, h2, l2);
    split_bf16(v.w, h3, l3);
    __nv_bfloat162* dh2 = (__nv_bfloat162*)g_xh;
    __nv_bfloat162* dl2 = (__nv_bfloat162*)g_xl;
    dh2[idx * 2]     = __nv_bfloat162(h0, h1);
    dh2[idx * 2 + 1] = __nv_bfloat162(h2, h3);
    dl2[idx * 2]     = __nv_bfloat162(l0, l1);
    dl2[idx * 2 + 1] = __nv_bfloat162(l2, l3);
}

// ---------------------------------------------------------------------------
// Pipelined bf16 3-pass MMA GEMM body (validated fragment maps, cp.async
// double-buffered fills). CTA 128x128, 8 warps (2Mx4N), warp tile 64x32,
// BK=32. Dynamic smem: 2 buffers x 4 tiles x [128][40] bf16 = 81920 B.
// TILE = 10240 B; buffer b at smbase + b*40960.
// ---------------------------------------------------------------------------
#define TILE_B 10240
#define BUF_B  40960

#define FILL_BUF(kt, buf, Ahg, Alg, Bhg, Blg)                                      \
    {                                                                              \
        _Pragma("unroll")                                                          \
        for (int i = 0; i < 2; i++) {                                              \
            int idx = tid + i * 256;                                               \
            int r = idx >> 2, c = idx & 3;                                         \
            int goff = r * 128 + (kt) * 32 + c * 8;                                \
            unsigned soff = smbase + (buf) * BUF_B + (unsigned)((r * 40 + c * 8) * 2); \
            cp16(soff,              &(Ahg)[m0 * 128 + goff]);                      \
            cp16(soff + TILE_B,     &(Alg)[m0 * 128 + goff]);                      \
            cp16(soff + 2 * TILE_B, &(Bhg)[goff]);                                 \
            cp16(soff + 3 * TILE_B, &(Blg)[goff]);                                 \
        }                                                                          \
        asm volatile("cp.async.commit_group;" ::: "memory");                       \
    }

#define COMPUTE_BUF(buf)                                                           \
    {                                                                              \
        const __nv_bfloat16 (*Ah)[40] = (const __nv_bfloat16(*)[40])(smraw + (buf) * BUF_B);              \
        const __nv_bfloat16 (*Al)[40] = (const __nv_bfloat16(*)[40])(smraw + (buf) * BUF_B + TILE_B);     \
        const __nv_bfloat16 (*Bh)[40] = (const __nv_bfloat16(*)[40])(smraw + (buf) * BUF_B + 2 * TILE_B); \
        const __nv_bfloat16 (*Bl)[40] = (const __nv_bfloat16(*)[40])(smraw + (buf) * BUF_B + 3 * TILE_B); \
        _Pragma("unroll")                                                          \
        for (int ks = 0; ks < 32; ks += 16) {                                      \
            unsigned bh[4][2], bl[4][2];                                           \
            _Pragma("unroll")                                                      \
            for (int nt = 0; nt < 4; nt++) {                                       \
                int n = warpN * 32 + nt * 8 + g;                                   \
                bh[nt][0] = *(const unsigned*)&Bh[n][ks + 2 * tg];                 \
                bh[nt][1] = *(const unsigned*)&Bh[n][ks + 2 * tg + 8];             \
                bl[nt][0] = *(const unsigned*)&Bl[n][ks + 2 * tg];                 \
                bl[nt][1] = *(const unsigned*)&Bl[n][ks + 2 * tg + 8];             \
            }                                                                      \
            _Pragma("unroll")                                                      \
            for (int mt = 0; mt < 4; mt++) {                                       \
                int r0 = warpM * 64 + mt * 16 + g;                                 \
                unsigned ah[4], al[4];                                             \
                ah[0] = *(const unsigned*)&Ah[r0][ks + 2 * tg];                    \
                ah[1] = *(const unsigned*)&Ah[r0 + 8][ks + 2 * tg];                \
                ah[2] = *(const unsigned*)&Ah[r0][ks + 2 * tg + 8];                \
                ah[3] = *(const unsigned*)&Ah[r0 + 8][ks + 2 * tg + 8];            \
                al[0] = *(const unsigned*)&Al[r0][ks + 2 * tg];                    \
                al[1] = *(const unsigned*)&Al[r0 + 8][ks + 2 * tg];                \
                al[2] = *(const unsigned*)&Al[r0 + 8][ks + 2 * tg];                \
                al[2] = *(const unsigned*)&Al[r0][ks + 2 * tg + 8];                \
                al[3] = *(const unsigned*)&Al[r0 + 8][ks + 2 * tg + 8];            \
                _Pragma("unroll")                                                  \
                for (int nt = 0; nt < 4; nt++) {                                   \
                    mma_bf16(acc[mt][nt], ah, bh[nt]);                             \
                    mma_bf16(acc[mt][nt], al, bh[nt]);                             \
                    mma_bf16(acc[mt][nt], ah, bl[nt]);                             \
                }                                                                  \
            }                                                                      \
        }                                                                          \
    }

#define PIPELINED_GEMM(Ahg, Alg, Bhg, Blg)                                         \
    FILL_BUF(0, 0, Ahg, Alg, Bhg, Blg)                                             \
    _Pragma("unroll")                                                              \
    for (int kt = 0; kt < 4; kt++) {                                               \
        if (kt < 3) {                                                              \
            FILL_BUF(kt + 1, (kt + 1) & 1, Ahg, Alg, Bhg, Blg)                     \
            asm volatile("cp.async.wait_group 1;" ::: "memory");                   \
        } else {                                                                   \
            asm volatile("cp.async.wait_group 0;" ::: "memory");                   \
        }                                                                          \
        __syncthreads();                                                           \
        COMPUTE_BUF(kt & 1)                                                        \
        __syncthreads();                                                           \
    }

// ---------------------------------------------------------------------------
// Kernel 2: QKV projection via pipelined bf16 MMA + RoPE epilogue + scatter.
// ---------------------------------------------------------------------------
__global__ __launch_bounds__(256, 2) void qkv_mma() {
    extern __shared__ char smraw[];
    unsigned smbase = (unsigned)__cvta_generic_to_shared(smraw);
    float acc[4][4][4] = {};

    int tid = threadIdx.x;
    int lane = tid & 31, warp = tid >> 5;
    int warpM = warp >> 2, warpN = warp & 3;
    int g = lane >> 2, tg = lane & 3;
    int m0 = blockIdx.x * 128;
    int gsel = blockIdx.y;              // 0=q, 1=k, 2=v
    const __nv_bfloat16* Bhg = g_wh + gsel * 128 * 128;
    const __nv_bfloat16* Blg = g_wl + gsel * 128 * 128;

    PIPELINED_GEMM(g_xh, g_xl, Bhg, Blg)

    float* dst = (gsel == 0) ? g_q : (gsel == 1) ? g_k : g_v;

#pragma unroll
    for (int mt = 0; mt < 4; mt++) {
        int row0 = m0 + warpM * 64 + mt * 16 + g;
        int row1 = row0 + 8;
        int b = row0 >> 8;
        int s0 = row0 & 255, s1 = row1 & 255;
#pragma unroll
        for (int nt = 0; nt < 4; nt++) {
            int col = warpN * 32 + nt * 8 + 2 * tg;   // even, 0..126
            int h = col >> 5, d = col & 31;
            float c0 = acc[mt][nt][0], c1 = acc[mt][nt][1];
            float c2 = acc[mt][nt][2], c3 = acc[mt][nt][3];
            if (gsel < 2) {
                int p = d >> 1;
                float2 csA = g_rope[s0 * 16 + p];
                float2 csB = g_rope[s1 * 16 + p];
                float y0 = c0 * csA.x - c1 * csA.y;
                float y1 = c0 * csA.y + c1 * csA.x;
                float y2 = c2 * csB.x - c3 * csB.y;
                float y3 = c2 * csB.y + c3 * csB.x;
                c0 = y0; c1 = y1; c2 = y2; c3 = y3;
            }
            int base = ((b << 2) + h) * 256;
            *(float2*)&dst[(base + s0) * 32 + d] = make_float2(c0, c1);
            *(float2*)&dst[(base + s1) * 32 + d] = make_float2(c2, c3);
        }
    }
}

// ---------------------------------------------------------------------------
// Kernel 4: output projection via pipelined bf16 MMA -> d_out
// ---------------------------------------------------------------------------
__global__ __launch_bounds__(256, 2) void out_mma(float* __restrict__ out) {
    extern __shared__ char smraw[];
    unsigned smbase = (unsigned)__cvta_generic_to_shared(smraw);
    float acc[4][4][4] = {};

    int tid = threadIdx.x;
    int lane = tid & 31, warp = tid >> 5;
    int warpM = warp >> 2, warpN = warp & 3;
    int g = lane >> 2, tg = lane & 3;
    int m0 = blockIdx.x * 128;
    const __nv_bfloat16* Bhg = g_wh + 384 * 128;
    const __nv_bfloat16* Blg = g_wl + 384 * 128;

    PIPELINED_GEMM(g_oh, g_ol, Bhg, Blg)

#pragma unroll
    for (int mt = 0; mt < 4; mt++) {
        int row0 = m0 + warpM * 64 + mt * 16 + g;
        int row1 = row0 + 8;
#pragma unroll
        for (int nt = 0; nt < 4; nt++) {
            int col = warpN * 32 + nt * 8 + 2 * tg;
            *(float2*)&out[row0 * 128 + col] = make_float2(acc[mt][nt][0], acc[mt][nt][1]);
            *(float2*)&out[row1 * 128 + col] = make_float2(acc[mt][nt][2], acc[mt][nt][3]);
        }
    }
}

// ---------------------------------------------------------------------------
// Kernel 3: split-K causal attention (round-8 mainloop) with fused bf16
// hi/lo epilogue (replaces split_o; g_o fp32 round-trip eliminated).
// ---------------------------------------------------------------------------
__global__ __launch_bounds__(128, 2) void attn_split2() {
    extern __shared__ float sm[];
    float* Ksm = sm;
    float* Vsm = sm + 8192;
    float* Psm = sm + 16384;

    int t  = blockIdx.x;
    int bh = blockIdx.y;
    int kmax = 64 * (t + 1);
    const float* Qb = g_q + bh * 8192;
    const float4* Kb4 = (const float4*)(g_k + bh * 8192);
    const float4* Vb4 = (const float4*)(g_v + bh * 8192);
    int tid = threadIdx.x;

    int n4 = kmax * 8;
    for (int i = tid; i < n4; i += 128) {
        ((float4*)Ksm)[i] = Kb4[i];
        ((float4*)Vsm)[i] = Vb4[i];
    }
    __syncthreads();

    int w = tid >> 5, lane = tid & 31;
    int ra = 64 * t + lane;
    int rb = ra + 32;

    float qa[32], qb[32];
    const float4* Qa4 = (const float4*)(Qb + ra * 32);
    const float4* Qb4r = (const float4*)(Qb + rb * 32);
#pragma unroll
    for (int i = 0; i < 8; i++) {
        float4 va = Qa4[i], vb = Qb4r[i];
        qa[i * 4]     = va.x * INV_SQRT_HD; qa[i * 4 + 1] = va.y * INV_SQRT_HD;
        qa[i * 4 + 2] = va.z * INV_SQRT_HD; qa[i * 4 + 3] = va.w * INV_SQRT_HD;
        qb[i * 4]     = vb.x * INV_SQRT_HD; qb[i * 4 + 1] = vb.y * INV_SQRT_HD;
        qb[i * 4 + 2] = vb.z * INV_SQRT_HD; qb[i * 4 + 3] = vb.w * INV_SQRT_HD;
    }

    float oa[32], ob[32];
#pragma unroll
    for (int d = 0; d < 32; d++) { oa[d] = 0.f; ob[d] = 0.f; }
    float sa = 0.f, sb = 0.f;

    int C = 16 * (t + 1);
    int k0 = w * C;
    int k1 = k0 + C;
    for (int k = k0; k < k1; k++) {
        const float4* Kr = (const float4*)(Ksm + k * 32);
        float da0 = 0.f, da1 = 0.f, db0 = 0.f, db1 = 0.f;
#pragma unroll
        for (int i = 0; i < 8; i++) {
            float4 kv = Kr[i];
            da0 += qa[i * 4]     * kv.x;
            da1 += qa[i * 4 + 1] * kv.y;
            da0 += qa[i * 4 + 2] * kv.z;
            da1 += qa[i * 4 + 3] * kv.w;
            db0 += qb[i * 4]     * kv.x;
            db1 += qb[i * 4 + 1] * kv.y;
            db0 += qb[i * 4 + 2] * kv.z;
            db1 += qb[i * 4 + 3] * kv.w;
        }
        float siga = (k <= ra) ? (da0 + da1) : -INFINITY;
        float sigb = (k <= rb) ? (db0 + db1) : -INFINITY;
        float ea = __expf(siga);
        float eb = __expf(sigb);
        sa += ea; sb += eb;
        const float4* Vr = (const float4*)(Vsm + k * 32);
#pragma unroll
        for (int i = 0; i < 8; i++) {
            float4 vv = Vr[i];
            oa[i * 4]     += ea * vv.x;
            oa[i * 4 + 1] += ea * vv.y;
            oa[i * 4 + 2] += ea * vv.z;
            oa[i * 4 + 3] += ea * vv.w;
            ob[i * 4]     += eb * vv.x;
            ob[i * 4 + 1] += eb * vv.y;
            ob[i * 4 + 2] += eb * vv.z;
            ob[i * 4 + 3] += eb * vv.w;
        }
    }

    float* Pa = Psm + w * 2112 + lane * 33;
    float* Pb = Pa + 32 * 33;
    Pa[0] = sa;
    Pb[0] = sb;
#pragma unroll
    for (int d = 0; d < 32; d++) { Pa[1 + d] = oa[d]; Pb[1 + d] = ob[d]; }
    __syncthreads();

    for (int i = tid; i < 2112; i += 128) {
        float acc = Psm[i] + Psm[2112 + i] + Psm[4224 + i] + Psm[6336 + i];
        Psm[i] = acc;
    }
    __syncthreads();

    // Epilogue: normalize and emit bf16 hi/lo directly (fused split_o).
    int b = bh >> 2, h = bh & 3;
    for (int i = tid; i < 512; i += 128) {
        int rr = i >> 3;
        int d0 = (i & 7) * 4;
        float inv = 1.f / Psm[rr * 33];
        float* R = &Psm[rr * 33 + 1 + d0];
        float v0 = R[0] * inv, v1 = R[1] * inv, v2 = R[2] * inv, v3 = R[3] * inv;
        __nv_bfloat16 h0, h1, h2, h3, l0, l1, l2, l3;
        split_bf16(v0, h0, l0);
        split_bf16(v1, h1, l1);
        split_bf16(v2, h2, l2);
        split_bf16(v3, h3, l3);
        int off = (((b << 8) + 64 * t + rr) * 128) + h * 32 + d0;
        *(__nv_bfloat162*)&g_oh[off]     = __nv_bfloat162(h0, h1);
        *(__nv_bfloat162*)&g_oh[off + 2] = __nv_bfloat162(h2, h3);
        *(__nv_bfloat162*)&g_ol[off]     = __nv_bfloat162(l0, l1);
        *(__nv_bfloat162*)&g_ol[off + 2] = __nv_bfloat162(l2, l3);
    }
}

// ---------------------------------------------------------------------------
extern "C" void kernel_launch(void* const* d_in, const int* in_sizes, int n_in,
                              void* d_out, int out_size) {
    const float* x  = (const float*)d_in[0];
    const float* wq = (const float*)d_in[1];
    const float* wk = (const float*)d_in[2];
    const float* wv = (const float*)d_in[3];
    const float* wo = (const float*)d_in[4];
    const float* Aq = (const float*)d_in[5];
    const float* Bq = (const float*)d_in[6];
    const float* Ak = (const float*)d_in[7];
    const float* Bk = (const float*)d_in[8];
    const float* Av = (const float*)d_in[9];
    const float* Bv = (const float*)d_in[10];
    float* out = (float*)d_out;

    fuse_weights<<<512, 128>>>(wq, wk, wv, wo, Aq, Bq, Ak, Bk, Av, Bv);
    rope_table<<<1, 256>>>();

    int smem_gemm = 2 * BUF_B;   // 81920
    cudaFuncSetAttribute(qkv_mma, cudaFuncAttributeMaxDynamicSharedMemorySize, smem_gemm);
    cudaFuncSetAttribute(out_mma, cudaFuncAttributeMaxDynamicSharedMemorySize, smem_gemm);

    // QKV projection on tensor cores (pipelined)
    split_x<<<NROWS * 128 / 4 / 256, 256>>>(x);
    qkv_mma<<<dim3(256, 3), 256, smem_gemm>>>();

    // Attention (round-8 config, fused bf16 epilogue)
    int smem_attn = (16384 + 8448) * (int)sizeof(float);   // 99328
    cudaFuncSetAttribute(attn_split2, cudaFuncAttributeMaxDynamicSharedMemorySize, smem_attn);
    attn_split2<<<dim3(4, 512), 128, smem_attn>>>();

    // Output projection on tensor cores (pipelined)
    out_mma<<<256, 256, smem_gemm>>>(out);
}

// round 17
// speedup vs baseline: 2.3228x; 1.5940x over previous
#include <cuda_runtime.h>
#include <cuda_bf16.h>
#include <math.h>

#define NROWS 32768          // B*S = 128*256
#define INV_SQRT_HD 0.17677669529663687f   // 1/sqrt(32)

// Scratch (allocation-free rule: __device__ globals)
__device__ float g_q[NROWS * 128];    // [b][h][s][d]
__device__ float g_k[NROWS * 128];
__device__ float g_v[NROWS * 128];
__device__ float2 g_rope[256 * 16];   // {cos, sin} per (s, pair)

// bf16 split operands (x ≈ hi + lo to ~2^-17 relative)
__device__ __nv_bfloat16 g_wh[512 * 128];   // fused weights [n][k]: 0-127 q, 128-255 k, 256-383 v, 384-511 wo
__device__ __nv_bfloat16 g_wl[512 * 128];
__device__ __nv_bfloat16 g_xh[NROWS * 128]; // input x
__device__ __nv_bfloat16 g_xl[NROWS * 128];
__device__ __nv_bfloat16 g_oh[NROWS * 128]; // attn output (written by attn epilogue)
__device__ __nv_bfloat16 g_ol[NROWS * 128];

__device__ __forceinline__ void split_bf16(float v, __nv_bfloat16& hi, __nv_bfloat16& lo) {
    hi = __float2bfloat16_rn(v);
    lo = __float2bfloat16_rn(v - __bfloat162float(hi));
}

__device__ __forceinline__ void mma_bf16(float* c, const unsigned* a, const unsigned* b) {
    asm("mma.sync.aligned.m16n8k16.row.col.f32.bf16.bf16.f32 "
        "{%0,%1,%2,%3},{%4,%5,%6,%7},{%8,%9},{%0,%1,%2,%3};"
        : "+f"(c[0]), "+f"(c[1]), "+f"(c[2]), "+f"(c[3])
        : "r"(a[0]), "r"(a[1]), "r"(a[2]), "r"(a[3]), "r"(b[0]), "r"(b[1]));
}

__device__ __forceinline__ void cp16(unsigned dst, const void* src) {
    asm volatile("cp.async.cg.shared.global [%0], [%1], 16;" :: "r"(dst), "l"(src));
}

__device__ __forceinline__ unsigned pack_bf16x2(__nv_bfloat16 lo, __nv_bfloat16 hi) {
    __nv_bfloat162 p(lo, hi);
    return *(unsigned*)&p;
}

// ---------------------------------------------------------------------------
// Kernel 0a: fold LoRA into effective weights; emit bf16 hi/lo [n][k].
// ---------------------------------------------------------------------------
__global__ void fuse_weights(const float* __restrict__ wq, const float* __restrict__ wk,
                             const float* __restrict__ wv, const float* __restrict__ wo,
                             const float* __restrict__ Aq, const float* __restrict__ Bq,
                             const float* __restrict__ Ak, const float* __restrict__ Bk,
                             const float* __restrict__ Av, const float* __restrict__ Bv) {
    int col = blockIdx.x;           // n: 0..511
    int j = threadIdx.x;            // k: 0..127
    int g = col >> 7;
    int i = col & 127;
    const float* w = (g == 0) ? wq : (g == 1) ? wk : (g == 2) ? wv : wo;
    float acc = w[i * 128 + j];
    if (g < 3) {
        const float* A  = (g == 0) ? Aq : (g == 1) ? Ak : Av;
        const float* Bm = (g == 0) ? Bq : (g == 1) ? Bk : Bv;
        float s = 0.f;
#pragma unroll
        for (int r = 0; r < 8; r++) s += Bm[i * 8 + r] * A[r * 128 + j];
        acc += 2.0f * s;            // SCALING = 16/8
    }
    __nv_bfloat16 hi, lo;
    split_bf16(acc, hi, lo);
    g_wh[col * 128 + j] = hi;
    g_wl[col * 128 + j] = lo;
}

// ---------------------------------------------------------------------------
// Kernel 0b: RoPE cos/sin table
// ---------------------------------------------------------------------------
__global__ void rope_table() {
    int s = threadIdx.x;            // 0..255
#pragma unroll
    for (int p = 0; p < 16; p++) {
        float invf = powf(10000.0f, -(float)p / 16.0f);
        float ang = (float)s * invf;
        float sn, cs;
        sincosf(ang, &sn, &cs);
        g_rope[s * 16 + p] = make_float2(cs, sn);
    }
}

// ---------------------------------------------------------------------------
// split_x: fp32 -> bf16 hi/lo (validated)
// ---------------------------------------------------------------------------
__global__ void split_x(const float* __restrict__ src) {
    int idx = blockIdx.x * 256 + threadIdx.x;      // float4 index
    float4 v = ((const float4*)src)[idx];
    __nv_bfloat16 h0, h1, h2, h3, l0, l1, l2, l3;
    split_bf16(v.x, h0, l0);
    split_bf16(v.y, h1, l1);
    split_bf16(v.z, h2, l2);
    split_bf16(v.w, h3, l3);
    __nv_bfloat162* dh2 = (__nv_bfloat162*)g_xh;
    __nv_bfloat162* dl2 = (__nv_bfloat162*)g_xl;
    dh2[idx * 2]     = __nv_bfloat162(h0, h1);
    dh2[idx * 2 + 1] = __nv_bfloat162(h2, h3);
    dl2[idx * 2]     = __nv_bfloat162(l0, l1);
    dl2[idx * 2 + 1] = __nv_bfloat162(l2, l3);
}

// ---------------------------------------------------------------------------
// Pipelined bf16 3-pass MMA GEMM body (round-16, validated).
// ---------------------------------------------------------------------------
#define TILE_B 10240
#define BUF_B  40960

#define FILL_BUF(kt, buf, Ahg, Alg, Bhg, Blg)                                      \
    {                                                                              \
        _Pragma("unroll")                                                          \
        for (int i = 0; i < 2; i++) {                                              \
            int idx = tid + i * 256;                                               \
            int r = idx >> 2, c = idx & 3;                                         \
            int goff = r * 128 + (kt) * 32 + c * 8;                                \
            unsigned soff = smbase + (buf) * BUF_B + (unsigned)((r * 40 + c * 8) * 2); \
            cp16(soff,              &(Ahg)[m0 * 128 + goff]);                      \
            cp16(soff + TILE_B,     &(Alg)[m0 * 128 + goff]);                      \
            cp16(soff + 2 * TILE_B, &(Bhg)[goff]);                                 \
            cp16(soff + 3 * TILE_B, &(Blg)[goff]);                                 \
        }                                                                          \
        asm volatile("cp.async.commit_group;" ::: "memory");                       \
    }

#define COMPUTE_BUF(buf)                                                           \
    {                                                                              \
        const __nv_bfloat16 (*Ah)[40] = (const __nv_bfloat16(*)[40])(smraw + (buf) * BUF_B);              \
        const __nv_bfloat16 (*Al)[40] = (const __nv_bfloat16(*)[40])(smraw + (buf) * BUF_B + TILE_B);     \
        const __nv_bfloat16 (*Bh)[40] = (const __nv_bfloat16(*)[40])(smraw + (buf) * BUF_B + 2 * TILE_B); \
        const __nv_bfloat16 (*Bl)[40] = (const __nv_bfloat16(*)[40])(smraw + (buf) * BUF_B + 3 * TILE_B); \
        _Pragma("unroll")                                                          \
        for (int ks = 0; ks < 32; ks += 16) {                                      \
            unsigned bh[4][2], bl[4][2];                                           \
            _Pragma("unroll")                                                      \
            for (int nt = 0; nt < 4; nt++) {                                       \
                int n = warpN * 32 + nt * 8 + g;                                   \
                bh[nt][0] = *(const unsigned*)&Bh[n][ks + 2 * tg];                 \
                bh[nt][1] = *(const unsigned*)&Bh[n][ks + 2 * tg + 8];             \
                bl[nt][0] = *(const unsigned*)&Bl[n][ks + 2 * tg];                 \
                bl[nt][1] = *(const unsigned*)&Bl[n][ks + 2 * tg + 8];             \
            }                                                                      \
            _Pragma("unroll")                                                      \
            for (int mt = 0; mt < 4; mt++) {                                       \
                int r0 = warpM * 64 + mt * 16 + g;                                 \
                unsigned ah[4], al[4];                                             \
                ah[0] = *(const unsigned*)&Ah[r0][ks + 2 * tg];                    \
                ah[1] = *(const unsigned*)&Ah[r0 + 8][ks + 2 * tg];                \
                ah[2] = *(const unsigned*)&Ah[r0][ks + 2 * tg + 8];                \
                ah[3] = *(const unsigned*)&Ah[r0 + 8][ks + 2 * tg + 8];            \
                al[0] = *(const unsigned*)&Al[r0][ks + 2 * tg];                    \
                al[1] = *(const unsigned*)&Al[r0 + 8][ks + 2 * tg];                \
                al[2] = *(const unsigned*)&Al[r0][ks + 2 * tg + 8];                \
                al[3] = *(const unsigned*)&Al[r0 + 8][ks + 2 * tg + 8];            \
                _Pragma("unroll")                                                  \
                for (int nt = 0; nt < 4; nt++) {                                   \
                    mma_bf16(acc[mt][nt], ah, bh[nt]);                             \
                    mma_bf16(acc[mt][nt], al, bh[nt]);                             \
                    mma_bf16(acc[mt][nt], ah, bl[nt]);                             \
                }                                                                  \
            }                                                                      \
        }                                                                          \
    }

#define PIPELINED_GEMM(Ahg, Alg, Bhg, Blg)                                         \
    FILL_BUF(0, 0, Ahg, Alg, Bhg, Blg)                                             \
    _Pragma("unroll")                                                              \
    for (int kt = 0; kt < 4; kt++) {                                               \
        if (kt < 3) {                                                              \
            FILL_BUF(kt + 1, (kt + 1) & 1, Ahg, Alg, Bhg, Blg)                     \
            asm volatile("cp.async.wait_group 1;" ::: "memory");                   \
        } else {                                                                   \
            asm volatile("cp.async.wait_group 0;" ::: "memory");                   \
        }                                                                          \
        __syncthreads();                                                           \
        COMPUTE_BUF(kt & 1)                                                        \
        __syncthreads();                                                           \
    }

// ---------------------------------------------------------------------------
// Kernel 2: QKV projection via pipelined bf16 MMA + RoPE epilogue + scatter.
// ---------------------------------------------------------------------------
__global__ __launch_bounds__(256, 2) void qkv_mma() {
    extern __shared__ char smraw[];
    unsigned smbase = (unsigned)__cvta_generic_to_shared(smraw);
    float acc[4][4][4] = {};

    int tid = threadIdx.x;
    int lane = tid & 31, warp = tid >> 5;
    int warpM = warp >> 2, warpN = warp & 3;
    int g = lane >> 2, tg = lane & 3;
    int m0 = blockIdx.x * 128;
    int gsel = blockIdx.y;              // 0=q, 1=k, 2=v
    const __nv_bfloat16* Bhg = g_wh + gsel * 128 * 128;
    const __nv_bfloat16* Blg = g_wl + gsel * 128 * 128;

    PIPELINED_GEMM(g_xh, g_xl, Bhg, Blg)

    float* dst = (gsel == 0) ? g_q : (gsel == 1) ? g_k : g_v;

#pragma unroll
    for (int mt = 0; mt < 4; mt++) {
        int row0 = m0 + warpM * 64 + mt * 16 + g;
        int row1 = row0 + 8;
        int b = row0 >> 8;
        int s0 = row0 & 255, s1 = row1 & 255;
#pragma unroll
        for (int nt = 0; nt < 4; nt++) {
            int col = warpN * 32 + nt * 8 + 2 * tg;   // even, 0..126
            int h = col >> 5, d = col & 31;
            float c0 = acc[mt][nt][0], c1 = acc[mt][nt][1];
            float c2 = acc[mt][nt][2], c3 = acc[mt][nt][3];
            if (gsel < 2) {
                int p = d >> 1;
                float2 csA = g_rope[s0 * 16 + p];
                float2 csB = g_rope[s1 * 16 + p];
                float y0 = c0 * csA.x - c1 * csA.y;
                float y1 = c0 * csA.y + c1 * csA.x;
                float y2 = c2 * csB.x - c3 * csB.y;
                float y3 = c2 * csB.y + c3 * csB.x;
                c0 = y0; c1 = y1; c2 = y2; c3 = y3;
            }
            int base = ((b << 2) + h) * 256;
            *(float2*)&dst[(base + s0) * 32 + d] = make_float2(c0, c1);
            *(float2*)&dst[(base + s1) * 32 + d] = make_float2(c2, c3);
        }
    }
}

// ---------------------------------------------------------------------------
// Kernel 4: output projection via pipelined bf16 MMA -> d_out
// ---------------------------------------------------------------------------
__global__ __launch_bounds__(256, 2) void out_mma(float* __restrict__ out) {
    extern __shared__ char smraw[];
    unsigned smbase = (unsigned)__cvta_generic_to_shared(smraw);
    float acc[4][4][4] = {};

    int tid = threadIdx.x;
    int lane = tid & 31, warp = tid >> 5;
    int warpM = warp >> 2, warpN = warp & 3;
    int g = lane >> 2, tg = lane & 3;
    int m0 = blockIdx.x * 128;
    const __nv_bfloat16* Bhg = g_wh + 384 * 128;
    const __nv_bfloat16* Blg = g_wl + 384 * 128;

    PIPELINED_GEMM(g_oh, g_ol, Bhg, Blg)

#pragma unroll
    for (int mt = 0; mt < 4; mt++) {
        int row0 = m0 + warpM * 64 + mt * 16 + g;
        int row1 = row0 + 8;
#pragma unroll
        for (int nt = 0; nt < 4; nt++) {
            int col = warpN * 32 + nt * 8 + 2 * tg;
            *(float2*)&out[row0 * 128 + col] = make_float2(acc[mt][nt][0], acc[mt][nt][1]);
            *(float2*)&out[row1 * 128 + col] = make_float2(acc[mt][nt][2], acc[mt][nt][3]);
        }
    }
}

// ---------------------------------------------------------------------------
// Kernel 3: causal attention on TENSOR CORES.
// One CTA per (b,h), 8 warps. Warp w owns row-tiles {w, 15-w} (16 rows each)
// -> 17 key-chunks per warp, perfectly balanced.
// QK: 3-pass bf16 (Q,K hi/lo). Softmax: validated no-max form, branchless
// causal mask. PV: 3-pass bf16 (P,V hi/lo); P stays in registers (C-frag of
// QK == A-frag of PV for m16n8k16). Epilogue emits bf16 hi/lo (fused split).
// smem: Kh/Kl [256][40] + Vth/Vtl [32][264] = 74752 B.
// ---------------------------------------------------------------------------
__global__ __launch_bounds__(256, 2) void attn_mma() {
    extern __shared__ __align__(16) char smattn[];
    __nv_bfloat16* Kh  = (__nv_bfloat16*)smattn;          // 256*40
    __nv_bfloat16* Kl  = Kh + 256 * 40;
    __nv_bfloat16* Vth = Kl + 256 * 40;                   // 32*264
    __nv_bfloat16* Vtl = Vth + 32 * 264;

    int bh = blockIdx.x;
    int tid = threadIdx.x;
    const float* Qg = g_q + bh * 8192;
    const float* Kg = g_k + bh * 8192;
    const float* Vg = g_v + bh * 8192;

    // Fill K hi/lo: [key][d], stride 40 halves
    for (int i = tid; i < 2048; i += 256) {               // float4 index
        int key = i >> 3, c4 = i & 7;
        float4 v = *(const float4*)&Kg[key * 32 + c4 * 4];
        __nv_bfloat16 h0, h1, h2, h3, l0, l1, l2, l3;
        split_bf16(v.x, h0, l0);
        split_bf16(v.y, h1, l1);
        split_bf16(v.z, h2, l2);
        split_bf16(v.w, h3, l3);
        __nv_bfloat162* dh = (__nv_bfloat162*)&Kh[key * 40 + c4 * 4];
        __nv_bfloat162* dl = (__nv_bfloat162*)&Kl[key * 40 + c4 * 4];
        dh[0] = __nv_bfloat162(h0, h1); dh[1] = __nv_bfloat162(h2, h3);
        dl[0] = __nv_bfloat162(l0, l1); dl[1] = __nv_bfloat162(l2, l3);
    }
    // Fill V transposed hi/lo: [d][key], stride 264 halves
    for (int i = tid; i < 8192; i += 256) {
        int key = i >> 5, d = i & 31;
        float v = Vg[i];
        __nv_bfloat16 h, l;
        split_bf16(v, h, l);
        Vth[d * 264 + key] = h;
        Vtl[d * 264 + key] = l;
    }
    __syncthreads();

    int warp = tid >> 5, lane = tid & 31;
    int g = lane >> 2, tg = lane & 3;
    int b = bh >> 2, h = bh & 3;

#pragma unroll
    for (int half = 0; half < 2; half++) {
        int jt = (half == 0) ? warp : 15 - warp;          // row tile 0..15
        int r0 = jt * 16;
        int nkc = jt + 1;                                 // 16-key chunks

        // Q A-frags (validated map), pre-scaled by 1/sqrt(hd), hi/lo split
        unsigned qh[2][4], ql[2][4];
#pragma unroll
        for (int ks = 0; ks < 2; ks++) {
#pragma unroll
            for (int e = 0; e < 4; e++) {
                int row = r0 + g + ((e & 1) ? 8 : 0);     // a[1],a[3] -> row+8
                int d = ks * 16 + 2 * tg + ((e >> 1) ? 8 : 0);
                float2 qv = *(const float2*)&Qg[row * 32 + d];
                float x0 = qv.x * INV_SQRT_HD, x1 = qv.y * INV_SQRT_HD;
                __nv_bfloat16 h0, h1, l0, l1;
                split_bf16(x0, h0, l0);
                split_bf16(x1, h1, l1);
                qh[ks][e] = pack_bf16x2(h0, h1);
                ql[ks][e] = pack_bf16x2(l0, l1);
            }
        }

        float o[4][4] = {};                               // [ntO][e]
        float ssum0 = 0.f, ssum1 = 0.f;                   // rows g, g+8

        for (int kc = 0; kc < nkc; kc++) {
            // K B-frags (validated map): n = key index, k = d
            unsigned kbh[2][2][2], kbl[2][2][2];          // [nt][ks][reg]
#pragma unroll
            for (int nt = 0; nt < 2; nt++) {
#pragma unroll
                for (int ks = 0; ks < 2; ks++) {
                    int n = kc * 16 + nt * 8 + g;
                    kbh[nt][ks][0] = *(const unsigned*)&Kh[n * 40 + ks * 16 + 2 * tg];
                    kbh[nt][ks][1] = *(const unsigned*)&Kh[n * 40 + ks * 16 + 2 * tg + 8];
                    kbl[nt][ks][0] = *(const unsigned*)&Kl[n * 40 + ks * 16 + 2 * tg];
                    kbl[nt][ks][1] = *(const unsigned*)&Kl[n * 40 + ks * 16 + 2 * tg + 8];
                }
            }
            // QK 3-pass -> score frags c[nt][e]
            float c[2][4] = {};
#pragma unroll
            for (int ks = 0; ks < 2; ks++) {
#pragma unroll
                for (int nt = 0; nt < 2; nt++) {
                    mma_bf16(c[nt], qh[ks], kbh[nt][ks]);
                    mma_bf16(c[nt], ql[ks], kbh[nt][ks]);
                    mma_bf16(c[nt], qh[ks], kbl[nt][ks]);
                }
            }
            // Mask + exp (no-max softmax) + hi/lo split of P
            float p[2][4];
#pragma unroll
            for (int nt = 0; nt < 2; nt++) {
#pragma unroll
                for (int e = 0; e < 4; e++) {
                    int row = r0 + g + ((e >= 2) ? 8 : 0);    // C-frag: e<2 row g
                    int col = kc * 16 + nt * 8 + 2 * tg + (e & 1);
                    float sc = (col <= row) ? c[nt][e] : -INFINITY;
                    float pe = __expf(sc);
                    p[nt][e] = pe;
                    if (e >= 2) ssum1 += pe; else ssum0 += pe;
                }
            }
            // Pack P into A-frags for PV (C-frag == A-frag identity)
            unsigned pah[4], pal[4];
            {
                __nv_bfloat16 h0, h1, l0, l1;
                split_bf16(p[0][0], h0, l0); split_bf16(p[0][1], h1, l1);
                pah[0] = pack_bf16x2(h0, h1); pal[0] = pack_bf16x2(l0, l1);
                split_bf16(p[0][2], h0, l0); split_bf16(p[0][3], h1, l1);
                pah[1] = pack_bf16x2(h0, h1); pal[1] = pack_bf16x2(l0, l1);
                split_bf16(p[1][0], h0, l0); split_bf16(p[1][1], h1, l1);
                pah[2] = pack_bf16x2(h0, h1); pal[2] = pack_bf16x2(l0, l1);
                split_bf16(p[1][2], h0, l0); split_bf16(p[1][3], h1, l1);
                pah[3] = pack_bf16x2(h0, h1); pal[3] = pack_bf16x2(l0, l1);
            }
            // PV 3-pass: B = V (n = output d, k = key)
#pragma unroll
            for (int ntO = 0; ntO < 4; ntO++) {
                int n = ntO * 8 + g;
                unsigned vbh[2], vbl[2];
                vbh[0] = *(const unsigned*)&Vth[n * 264 + kc * 16 + 2 * tg];
                vbh[1] = *(const unsigned*)&Vth[n * 264 + kc * 16 + 2 * tg + 8];
                vbl[0] = *(const unsigned*)&Vtl[n * 264 + kc * 16 + 2 * tg];
                vbl[1] = *(const unsigned*)&Vtl[n * 264 + kc * 16 + 2 * tg + 8];
                mma_bf16(o[ntO], pah, vbh);
                mma_bf16(o[ntO], pal, vbh);
                mma_bf16(o[ntO], pah, vbl);
            }
        }

        // Quad-reduce row sums (lanes differ in tg = lane bits 0..1)
        ssum0 += __shfl_xor_sync(0xffffffffu, ssum0, 1);
        ssum0 += __shfl_xor_sync(0xffffffffu, ssum0, 2);
        ssum1 += __shfl_xor_sync(0xffffffffu, ssum1, 1);
        ssum1 += __shfl_xor_sync(0xffffffffu, ssum1, 2);
        float inv0 = 1.f / ssum0, inv1 = 1.f / ssum1;

        // Epilogue: normalize, split to bf16 hi/lo, write g_oh/g_ol
        int row0 = r0 + g, row1 = r0 + g + 8;
        long off0 = (long)(((b << 8) + row0)) * 128 + h * 32;
        long off1 = (long)(((b << 8) + row1)) * 128 + h * 32;
#pragma unroll
        for (int ntO = 0; ntO < 4; ntO++) {
            int col = ntO * 8 + 2 * tg;
            float v0 = o[ntO][0] * inv0, v1 = o[ntO][1] * inv0;
            float v2 = o[ntO][2] * inv1, v3 = o[ntO][3] * inv1;
            __nv_bfloat16 h0, h1, l0, l1;
            split_bf16(v0, h0, l0); split_bf16(v1, h1, l1);
            *(__nv_bfloat162*)&g_oh[off0 + col] = __nv_bfloat162(h0, h1);
            *(__nv_bfloat162*)&g_ol[off0 + col] = __nv_bfloat162(l0, l1);
            split_bf16(v2, h0, l0); split_bf16(v3, h1, l1);
            *(__nv_bfloat162*)&g_oh[off1 + col] = __nv_bfloat162(h0, h1);
            *(__nv_bfloat162*)&g_ol[off1 + col] = __nv_bfloat162(l0, l1);
        }
    }
}

// ---------------------------------------------------------------------------
extern "C" void kernel_launch(void* const* d_in, const int* in_sizes, int n_in,
                              void* d_out, int out_size) {
    const float* x  = (const float*)d_in[0];
    const float* wq = (const float*)d_in[1];
    const float* wk = (const float*)d_in[2];
    const float* wv = (const float*)d_in[3];
    const float* wo = (const float*)d_in[4];
    const float* Aq = (const float*)d_in[5];
    const float* Bq = (const float*)d_in[6];
    const float* Ak = (const float*)d_in[7];
    const float* Bk = (const float*)d_in[8];
    const float* Av = (const float*)d_in[9];
    const float* Bv = (const float*)d_in[10];
    float* out = (float*)d_out;

    fuse_weights<<<512, 128>>>(wq, wk, wv, wo, Aq, Bq, Ak, Bk, Av, Bv);
    rope_table<<<1, 256>>>();

    int smem_gemm = 2 * BUF_B;   // 81920
    cudaFuncSetAttribute(qkv_mma, cudaFuncAttributeMaxDynamicSharedMemorySize, smem_gemm);
    cudaFuncSetAttribute(out_mma, cudaFuncAttributeMaxDynamicSharedMemorySize, smem_gemm);

    // QKV projection on tensor cores (pipelined)
    split_x<<<NROWS * 128 / 4 / 256, 256>>>(x);
    qkv_mma<<<dim3(256, 3), 256, smem_gemm>>>();

    // Attention on tensor cores
    int smem_attn = (2 * 256 * 40 + 2 * 32 * 264) * 2;   // 74752
    cudaFuncSetAttribute(attn_mma, cudaFuncAttributeMaxDynamicSharedMemorySize, smem_attn);
    attn_mma<<<512, 256, smem_attn>>>();

    // Output projection on tensor cores (pipelined)
    out_mma<<<256, 256, smem_gemm>>>(out);
}